// round 1
// baseline (speedup 1.0000x reference)
#include <cuda_runtime.h>
#include <math.h>

#define D_MODEL 1024
#define S_LEN   1024
#define BATCH   4
#define NTOK    4096
#define NHEADS  16
#define HD      64
#define NRULES  64
#define RANK    8
#define SRANK   32
#define NBLK    16
#define TOPK    32

#define NEGINF (__int_as_float(0xff800000))

// ---------------- scratch (device globals; no allocation allowed) ------------
__device__ float g_T1[NTOK * SRANK];
__device__ float g_Q [NTOK * D_MODEL];
__device__ float g_K [NTOK * D_MODEL];
__device__ float g_V [NTOK * D_MODEL];
__device__ float g_AO[NTOK * D_MODEL];
__device__ float g_A [NRULES * NRULES];
__device__ float g_thr[NTOK];

// ---------------- affinity table: A[i][j] = <nrm(rq_i), nrm(rk_j)> * log(8) --
__global__ void aff_kernel(const float* __restrict__ rq, const float* __restrict__ rk,
                           float* __restrict__ A) {
    int idx = blockIdx.x * blockDim.x + threadIdx.x;
    if (idx >= NRULES * NRULES) return;
    int i = idx >> 6, j = idx & 63;
    float qv[RANK], kv[RANK];
    float nq = 0.f, nk = 0.f;
#pragma unroll
    for (int r = 0; r < RANK; r++) {
        qv[r] = rq[i * RANK + r]; kv[r] = rk[j * RANK + r];
        nq += qv[r] * qv[r];      nk += kv[r] * kv[r];
    }
    float iq = 1.f / fmaxf(sqrtf(nq), 1e-12f);
    float ik = 1.f / fmaxf(sqrtf(nk), 1e-12f);
    float dot = 0.f;
#pragma unroll
    for (int r = 0; r < RANK; r++) dot += (qv[r] * iq) * (kv[r] * ik);
    A[idx] = dot * 2.0794415416798357f;   // / tau, tau = 1/ln(8)
}

// --------- per-(b,q) top-32 threshold via rule histogram order statistic -----
__global__ void thr_kernel(const int* __restrict__ rules, const float* __restrict__ A,
                           float* __restrict__ thr) {
    int b = blockIdx.x >> 10;
    int q = blockIdx.x & 1023;
    __shared__ int   cnt[NRULES];
    __shared__ float row[NRULES];
    int t = threadIdx.x;      // 64 threads
    cnt[t] = 0;
    __syncthreads();
    const int* rb = rules + b * S_LEN;
    for (int k = t; k <= q; k += 64) atomicAdd(&cnt[rb[k]], 1);
    int rqid = rb[q];
    row[t] = A[rqid * NRULES + t];
    __syncthreads();
    if (q < TOPK - 1) {            // fewer than 32 finite entries -> thr = -inf
        if (t == 0) thr[blockIdx.x] = NEGINF;
        return;
    }
    float v = row[t];
    int   c = cnt[t];
    int greater = 0;
#pragma unroll 8
    for (int r = 0; r < NRULES; r++) greater += (row[r] > v) ? cnt[r] : 0;
    if (c > 0 && greater < TOPK && greater + c >= TOPK)
        thr[blockIdx.x] = v;       // ties write identical value
}

// ---------------- GEMM1: C[4096,32] = A[4096,1024] * B[1024,32] --------------
__global__ void gemm_k1024_n32(const float* __restrict__ Am, const float* __restrict__ Bm,
                               float* __restrict__ C) {
    __shared__ float As[64][33];
    __shared__ float Bs[32][33];
    int tid = threadIdx.x;
    int tx = tid & 31, ty = tid >> 5;     // ty in 0..7
    int rowBase = blockIdx.x * 64;
    float acc[8];
#pragma unroll
    for (int i = 0; i < 8; i++) acc[i] = 0.f;
    for (int k0 = 0; k0 < 1024; k0 += 32) {
#pragma unroll
        for (int i = 0; i < 8; i++) {
            int idx = tid + i * 256; int r = idx >> 5, kk = idx & 31;
            As[r][kk] = Am[(rowBase + r) * 1024 + k0 + kk];
        }
#pragma unroll
        for (int i = 0; i < 4; i++) {
            int idx = tid + i * 256; int r = idx >> 5, c = idx & 31;
            Bs[r][c] = Bm[(k0 + r) * 32 + c];
        }
        __syncthreads();
#pragma unroll
        for (int kk = 0; kk < 32; kk++) {
            float bv = Bs[kk][tx];
#pragma unroll
            for (int i = 0; i < 8; i++) acc[i] += As[ty + 8 * i][kk] * bv;
        }
        __syncthreads();
    }
#pragma unroll
    for (int i = 0; i < 8; i++)
        C[(rowBase + ty + 8 * i) * 32 + tx] = acc[i];
}

// ---------------- GEMM2: C[4096,1024] = A[4096,32] * B[32,1024] --------------
__global__ void gemm_k32_n1024(const float* __restrict__ Am, const float* __restrict__ Bm,
                               float* __restrict__ C) {
    __shared__ float As[64][33];
    __shared__ float Bs[32][65];
    int tid = threadIdx.x;
    int tx = tid & 15, ty = tid >> 4;     // 16x16
    int rowBase = blockIdx.x * 64, colBase = blockIdx.y * 64;
#pragma unroll
    for (int i = 0; i < 8; i++) {
        int idx = tid + i * 256;
        As[idx >> 5][idx & 31] = Am[(rowBase + (idx >> 5)) * 32 + (idx & 31)];
    }
#pragma unroll
    for (int i = 0; i < 8; i++) {
        int idx = tid + i * 256;
        Bs[idx >> 6][idx & 63] = Bm[(idx >> 6) * 1024 + colBase + (idx & 63)];
    }
    __syncthreads();
    float acc[4][4];
#pragma unroll
    for (int i = 0; i < 4; i++)
#pragma unroll
        for (int j = 0; j < 4; j++) acc[i][j] = 0.f;
#pragma unroll
    for (int kk = 0; kk < 32; kk++) {
        float a[4], bb[4];
#pragma unroll
        for (int i = 0; i < 4; i++) a[i] = As[ty + 16 * i][kk];
#pragma unroll
        for (int j = 0; j < 4; j++) bb[j] = Bs[kk][tx + 16 * j];
#pragma unroll
        for (int i = 0; i < 4; i++)
#pragma unroll
            for (int j = 0; j < 4; j++) acc[i][j] += a[i] * bb[j];
    }
#pragma unroll
    for (int i = 0; i < 4; i++)
#pragma unroll
        for (int j = 0; j < 4; j++)
            C[(rowBase + ty + 16 * i) * 1024 + colBase + tx + 16 * j] = acc[i][j];
}

// -------- adapter: out = base + (block-lowrank) * sel, optional RoPE ---------
__global__ void adapter_kernel(const float* __restrict__ X, float* __restrict__ Base,
                               const int* __restrict__ rules,
                               const float* __restrict__ ri, const float* __restrict__ ro,
                               const float* __restrict__ lg, int do_rope) {
    __shared__ float xs[D_MODEL];
    __shared__ float ris[HD * RANK];     // [64][8]
    __shared__ float ros[RANK * HD];     // [8][64]
    __shared__ float hs[NBLK * RANK];    // [16][8]
    __shared__ float sels[NBLK];
    int n = blockIdx.x;
    int t = threadIdx.x;                 // 128 threads
    int rule = rules[n];

    const float4* x4 = (const float4*)(X + (size_t)n * D_MODEL);
    float4* xs4 = (float4*)xs;
    xs4[t] = x4[t];
    xs4[t + 128] = x4[t + 128];
#pragma unroll
    for (int i = 0; i < 4; i++) {
        ris[t + i * 128] = ri[rule * 512 + t + i * 128];
        ros[t + i * 128] = ro[rule * 512 + t + i * 128];
    }
    if (t < 32) {
        int j = t & 15;
        float v = lg[rule * NBLK + j] * 4.0f;   // * sqrt(16)
        float mx = v;
#pragma unroll
        for (int msk = 8; msk >= 1; msk >>= 1)
            mx = fmaxf(mx, __shfl_xor_sync(0xffffffffu, mx, msk));
        float e = expf(v - mx);
        float sm = e;
#pragma unroll
        for (int msk = 8; msk >= 1; msk >>= 1)
            sm += __shfl_xor_sync(0xffffffffu, sm, msk);
        if (t < 16) sels[t] = e / sm;
    }
    __syncthreads();
    {
        int blk = t >> 3, r = t & 7;
        float sum = 0.f;
#pragma unroll
        for (int sx = 0; sx < 64; sx++) sum += xs[blk * 64 + sx] * ris[sx * 8 + r];
        hs[t] = sum;
    }
    __syncthreads();
    int d0 = t * 8;
    int blk = t >> 3;
    float hl[8];
#pragma unroll
    for (int r = 0; r < 8; r++) hl[r] = hs[blk * 8 + r];
    float selv = sels[blk];
    int spos = n & (S_LEN - 1);
    float outv[8];
#pragma unroll
    for (int c = 0; c < 8; c++) {
        int dh = (d0 + c) & 63;
        float a = 0.f;
#pragma unroll
        for (int r = 0; r < 8; r++) a += hl[r] * ros[r * 64 + dh];
        outv[c] = Base[(size_t)n * D_MODEL + d0 + c] + a * selv;
    }
    if (do_rope) {
#pragma unroll
        for (int p = 0; p < 4; p++) {
            int dh = (d0 + 2 * p) & 63;
            int i = dh >> 1;
            float div = expf((float)(2 * i) * (-0.14391156831212786f)); // -ln(1e4)/64
            float ang = (float)spos * div;
            float sn, cs;
            sincosf(ang, &sn, &cs);
            float t1 = outv[2 * p], t2 = outv[2 * p + 1];
            outv[2 * p]     = t1 * cs - t2 * sn;
            outv[2 * p + 1] = t2 * cs + t1 * sn;
        }
    }
#pragma unroll
    for (int c = 0; c < 8; c++) Base[(size_t)n * D_MODEL + d0 + c] = outv[c];
}

// ------------------------- flash attention (fp32) ----------------------------
__global__ void flash_kernel(const float* __restrict__ Q, const float* __restrict__ K,
                             const float* __restrict__ V, const int* __restrict__ rules,
                             const float* __restrict__ Atab, const float* __restrict__ thr,
                             float* __restrict__ O) {
    extern __shared__ float sm[];
    float* As    = sm;                 // 4096
    float* qs    = As + 4096;          // 64*65
    float* ks    = qs + 64 * 65;
    float* vs    = ks + 64 * 65;
    float* ps    = vs + 64 * 65;
    float* thr_s = ps + 64 * 65;       // 64
    int*   rq_s  = (int*)(thr_s + 64); // 64
    int*   rk_s  = rq_s + 64;          // 64

    int tid = threadIdx.x;
    int qt = blockIdx.x;
    int b  = blockIdx.y >> 4;
    int h  = blockIdx.y & 15;
    int tokBase = b * S_LEN;

#pragma unroll
    for (int i = 0; i < 16; i++) As[tid + i * 256] = Atab[tid + i * 256];
#pragma unroll
    for (int i = 0; i < 4; i++) {
        int idx = tid + i * 256; int r = idx >> 4, c4 = (idx & 15) * 4;
        float4 v4 = *(const float4*)(Q + (size_t)(tokBase + qt * 64 + r) * D_MODEL + h * 64 + c4);
        qs[r * 65 + c4] = v4.x; qs[r * 65 + c4 + 1] = v4.y;
        qs[r * 65 + c4 + 2] = v4.z; qs[r * 65 + c4 + 3] = v4.w;
    }
    if (tid < 64) {
        rq_s[tid]  = rules[tokBase + qt * 64 + tid];
        thr_s[tid] = thr[tokBase + qt * 64 + tid];
    }
    __syncthreads();

    int ty = tid >> 4, tx = tid & 15;
    float m[4], l[4], o[4][4];
#pragma unroll
    for (int i = 0; i < 4; i++) {
        m[i] = NEGINF; l[i] = 0.f;
#pragma unroll
        for (int j = 0; j < 4; j++) o[i][j] = 0.f;
    }

    for (int kt = 0; kt <= qt; kt++) {
#pragma unroll
        for (int i = 0; i < 4; i++) {
            int idx = tid + i * 256; int r = idx >> 4, c4 = (idx & 15) * 4;
            size_t g = (size_t)(tokBase + kt * 64 + r) * D_MODEL + h * 64 + c4;
            float4 kv4 = *(const float4*)(K + g);
            ks[r * 65 + c4] = kv4.x; ks[r * 65 + c4 + 1] = kv4.y;
            ks[r * 65 + c4 + 2] = kv4.z; ks[r * 65 + c4 + 3] = kv4.w;
            float4 vv4 = *(const float4*)(V + g);
            vs[r * 65 + c4] = vv4.x; vs[r * 65 + c4 + 1] = vv4.y;
            vs[r * 65 + c4 + 2] = vv4.z; vs[r * 65 + c4 + 3] = vv4.w;
        }
        if (tid < 64) rk_s[tid] = rules[tokBase + kt * 64 + tid];
        __syncthreads();

        float s[4][4];
#pragma unroll
        for (int i = 0; i < 4; i++)
#pragma unroll
            for (int j = 0; j < 4; j++) s[i][j] = 0.f;
#pragma unroll 8
        for (int d = 0; d < 64; d++) {
            float qv[4], kv[4];
#pragma unroll
            for (int i = 0; i < 4; i++) qv[i] = qs[(ty + 16 * i) * 65 + d];
#pragma unroll
            for (int j = 0; j < 4; j++) kv[j] = ks[(tx + 16 * j) * 65 + d];
#pragma unroll
            for (int i = 0; i < 4; i++)
#pragma unroll
                for (int j = 0; j < 4; j++) s[i][j] += qv[i] * kv[j];
        }
        // mask + scale
#pragma unroll
        for (int i = 0; i < 4; i++) {
            int r = qt * 64 + ty + 16 * i;
            float th = thr_s[ty + 16 * i];
            int rqi = rq_s[ty + 16 * i];
#pragma unroll
            for (int j = 0; j < 4; j++) {
                int c = kt * 64 + tx + 16 * j;
                float aff = As[rqi * 64 + rk_s[tx + 16 * j]];
                bool ok = (c <= r) && (aff >= th);
                s[i][j] = ok ? s[i][j] * 0.125f : NEGINF;
            }
        }
        // online softmax
#pragma unroll
        for (int i = 0; i < 4; i++) {
            float mx = fmaxf(fmaxf(s[i][0], s[i][1]), fmaxf(s[i][2], s[i][3]));
#pragma unroll
            for (int msk = 8; msk >= 1; msk >>= 1)
                mx = fmaxf(mx, __shfl_xor_sync(0xffffffffu, mx, msk));
            float mnew = fmaxf(m[i], mx);
            float corr = (m[i] == mnew) ? 1.0f : __expf(m[i] - mnew);
            float rs = 0.f;
#pragma unroll
            for (int j = 0; j < 4; j++) {
                float p = (s[i][j] == NEGINF) ? 0.0f : __expf(s[i][j] - mnew);
                s[i][j] = p; rs += p;
            }
#pragma unroll
            for (int msk = 8; msk >= 1; msk >>= 1)
                rs += __shfl_xor_sync(0xffffffffu, rs, msk);
            l[i] = l[i] * corr + rs;
#pragma unroll
            for (int j = 0; j < 4; j++) o[i][j] *= corr;
            m[i] = mnew;
#pragma unroll
            for (int j = 0; j < 4; j++) ps[(ty + 16 * i) * 65 + tx + 16 * j] = s[i][j];
        }
        __syncthreads();
        // PV
#pragma unroll 8
        for (int kk = 0; kk < 64; kk++) {
            float pv[4], vv[4];
#pragma unroll
            for (int i = 0; i < 4; i++) pv[i] = ps[(ty + 16 * i) * 65 + kk];
#pragma unroll
            for (int j = 0; j < 4; j++) vv[j] = vs[kk * 65 + tx + 16 * j];
#pragma unroll
            for (int i = 0; i < 4; i++)
#pragma unroll
                for (int j = 0; j < 4; j++) o[i][j] += pv[i] * vv[j];
        }
        __syncthreads();
    }
#pragma unroll
    for (int i = 0; i < 4; i++) {
        float inv = 1.0f / l[i];
#pragma unroll
        for (int j = 0; j < 4; j++)
            O[(size_t)(tokBase + qt * 64 + ty + 16 * i) * D_MODEL + h * 64 + tx + 16 * j] =
                o[i][j] * inv;
    }
}

// ----------------------------------------------------------------------------
extern "C" void kernel_launch(void* const* d_in, const int* in_sizes, int n_in,
                              void* d_out, int out_size) {
    const float* x     = (const float*)d_in[0];
    const int*   rules = (const int*)  d_in[1];
    const float* q_si = (const float*)d_in[2],  *q_so = (const float*)d_in[3];
    const float* q_ri = (const float*)d_in[4],  *q_ro = (const float*)d_in[5];
    const float* q_lg = (const float*)d_in[6];
    const float* k_si = (const float*)d_in[7],  *k_so = (const float*)d_in[8];
    const float* k_ri = (const float*)d_in[9],  *k_ro = (const float*)d_in[10];
    const float* k_lg = (const float*)d_in[11];
    const float* v_si = (const float*)d_in[12], *v_so = (const float*)d_in[13];
    const float* v_ri = (const float*)d_in[14], *v_ro = (const float*)d_in[15];
    const float* v_lg = (const float*)d_in[16];
    const float* o_si = (const float*)d_in[17], *o_so = (const float*)d_in[18];
    const float* o_ri = (const float*)d_in[19], *o_ro = (const float*)d_in[20];
    const float* o_lg = (const float*)d_in[21];
    const float* router_q = (const float*)d_in[22];
    const float* router_k = (const float*)d_in[23];
    float* out = (float*)d_out;

    float *T1, *Qb, *Kb, *Vb, *AO, *Atab, *Thr;
    cudaGetSymbolAddress((void**)&T1,   g_T1);
    cudaGetSymbolAddress((void**)&Qb,   g_Q);
    cudaGetSymbolAddress((void**)&Kb,   g_K);
    cudaGetSymbolAddress((void**)&Vb,   g_V);
    cudaGetSymbolAddress((void**)&AO,   g_AO);
    cudaGetSymbolAddress((void**)&Atab, g_A);
    cudaGetSymbolAddress((void**)&Thr,  g_thr);

    aff_kernel<<<16, 256>>>(router_q, router_k, Atab);
    thr_kernel<<<NTOK, 64>>>(rules, Atab, Thr);

    // Q projection
    gemm_k1024_n32<<<64, 256>>>(x, q_si, T1);
    gemm_k32_n1024<<<dim3(64, 16), 256>>>(T1, q_so, Qb);
    adapter_kernel<<<NTOK, 128>>>(x, Qb, rules, q_ri, q_ro, q_lg, 1);
    // K projection
    gemm_k1024_n32<<<64, 256>>>(x, k_si, T1);
    gemm_k32_n1024<<<dim3(64, 16), 256>>>(T1, k_so, Kb);
    adapter_kernel<<<NTOK, 128>>>(x, Kb, rules, k_ri, k_ro, k_lg, 1);
    // V projection
    gemm_k1024_n32<<<64, 256>>>(x, v_si, T1);
    gemm_k32_n1024<<<dim3(64, 16), 256>>>(T1, v_so, Vb);
    adapter_kernel<<<NTOK, 128>>>(x, Vb, rules, v_ri, v_ro, v_lg, 0);

    // flash attention
    size_t smem = (4096 + 4 * 64 * 65 + 64) * sizeof(float) + 128 * sizeof(int);
    cudaFuncSetAttribute(flash_kernel, cudaFuncAttributeMaxDynamicSharedMemorySize, (int)smem);
    flash_kernel<<<dim3(16, 64), 256, smem>>>(Qb, Kb, Vb, rules, Atab, Thr, AO);

    // O projection (base written directly into d_out, adapter in-place)
    gemm_k1024_n32<<<64, 256>>>(AO, o_si, T1);
    gemm_k32_n1024<<<dim3(64, 16), 256>>>(T1, o_so, out);
    adapter_kernel<<<NTOK, 128>>>(AO, out, rules, o_ri, o_ro, o_lg, 0);
}

// round 2
// speedup vs baseline: 1.6388x; 1.6388x over previous
#include <cuda_runtime.h>
#include <math.h>

#define D_MODEL 1024
#define S_LEN   1024
#define BATCH   4
#define NTOK    4096
#define NHEADS  16
#define HD      64
#define NRULES  64
#define RANK    8
#define SRANK   32
#define NBLK    16
#define TOPK    32

#define NEGINF (__int_as_float(0xff800000))

// ---------------- scratch (device globals; no allocation allowed) ------------
__device__ float g_T1[3 * NTOK * SRANK];
__device__ float g_Q [NTOK * D_MODEL];
__device__ float g_K [NTOK * D_MODEL];
__device__ float g_V [NTOK * D_MODEL];
__device__ float g_AO[NTOK * D_MODEL];
__device__ float g_A [NRULES * NRULES];
__device__ unsigned long long g_allow[NTOK];

__device__ __forceinline__ unsigned f2tf(float x) {
    unsigned u;
    asm("cvt.rna.tf32.f32 %0, %1;" : "=r"(u) : "f"(x));
    return u;
}

__device__ __forceinline__ void mma_tf32(float d[4], const unsigned a[4],
                                         unsigned b0, unsigned b1) {
    asm volatile(
        "mma.sync.aligned.m16n8k8.row.col.f32.tf32.tf32.f32 "
        "{%0,%1,%2,%3}, {%4,%5,%6,%7}, {%8,%9}, {%0,%1,%2,%3};\n"
        : "+f"(d[0]), "+f"(d[1]), "+f"(d[2]), "+f"(d[3])
        : "r"(a[0]), "r"(a[1]), "r"(a[2]), "r"(a[3]), "r"(b0), "r"(b1));
}

// ---------------- affinity table ---------------------------------------------
__global__ void aff_kernel(const float* __restrict__ rq, const float* __restrict__ rk,
                           float* __restrict__ A) {
    int idx = blockIdx.x * blockDim.x + threadIdx.x;
    if (idx >= NRULES * NRULES) return;
    int i = idx >> 6, j = idx & 63;
    float qv[RANK], kv[RANK];
    float nq = 0.f, nk = 0.f;
#pragma unroll
    for (int r = 0; r < RANK; r++) {
        qv[r] = rq[i * RANK + r]; kv[r] = rk[j * RANK + r];
        nq += qv[r] * qv[r];      nk += kv[r] * kv[r];
    }
    float iq = 1.f / fmaxf(sqrtf(nq), 1e-12f);
    float ik = 1.f / fmaxf(sqrtf(nk), 1e-12f);
    float dot = 0.f;
#pragma unroll
    for (int r = 0; r < RANK; r++) dot += (qv[r] * iq) * (kv[r] * ik);
    A[idx] = dot * 2.0794415416798357f;   // / tau
}

// --------- per-(b,q): top-32 threshold + allowed-rule 64-bit mask ------------
__global__ void thr_allow_kernel(const int* __restrict__ rules, const float* __restrict__ A,
                                 unsigned long long* __restrict__ allow) {
    int bq = blockIdx.x;
    int b = bq >> 10, q = bq & 1023;
    __shared__ int   cnt[NRULES];
    __shared__ float row[NRULES];
    __shared__ float thr_s;
    __shared__ unsigned bits[2];
    int t = threadIdx.x;      // 64 threads
    cnt[t] = 0;
    if (t == 0) thr_s = NEGINF;
    __syncthreads();
    const int* rb = rules + b * S_LEN;
    for (int k = t; k <= q; k += 64) atomicAdd(&cnt[rb[k]], 1);
    row[t] = A[rb[q] * NRULES + t];
    __syncthreads();
    if (q >= TOPK - 1) {
        float v = row[t];
        int   c = cnt[t];
        int greater = 0;
#pragma unroll 8
        for (int r = 0; r < NRULES; r++) greater += (row[r] > v) ? cnt[r] : 0;
        if (c > 0 && greater < TOPK && greater + c >= TOPK)
            thr_s = v;       // ties write identical value
    }
    __syncthreads();
    unsigned bal = __ballot_sync(0xffffffffu, row[t] >= thr_s);
    if ((t & 31) == 0) bits[t >> 5] = bal;
    __syncthreads();
    if (t == 0)
        allow[bq] = (unsigned long long)bits[0] | ((unsigned long long)bits[1] << 32);
}

// ---------------- GEMM1: T[z][4096,32] = X[4096,1024] * W_z[1024,32] ---------
__global__ void __launch_bounds__(128)
gemm1_kernel(const float* __restrict__ X, const float* __restrict__ W0,
             const float* __restrict__ W1, const float* __restrict__ W2,
             float* __restrict__ T) {
    __shared__ float As[64][36];
    __shared__ float Bt[32][36];
    int tid = threadIdx.x;
    int tx = tid & 7, ty = tid >> 3;       // tx: col/4 (8), ty: row grp (16)
    int z = blockIdx.z;
    const float* W = (z == 0) ? W0 : (z == 1) ? W1 : W2;
    float* C = T + (size_t)z * NTOK * SRANK;
    int rowBase = blockIdx.x * 64;
    float acc[4][4];
#pragma unroll
    for (int i = 0; i < 4; i++)
#pragma unroll
        for (int j = 0; j < 4; j++) acc[i][j] = 0.f;

    for (int k0 = 0; k0 < D_MODEL; k0 += 32) {
#pragma unroll
        for (int i = 0; i < 4; i++) {            // A: 64x32 as 512 float4
            int f = tid + i * 128;
            int r = f >> 3, kq = f & 7;
            float4 v = *(const float4*)(X + (size_t)(rowBase + r) * D_MODEL + k0 + kq * 4);
            *(float4*)&As[r][kq * 4] = v;
        }
#pragma unroll
        for (int i = 0; i < 8; i++) {            // B transposed: 32x32
            int f = tid + i * 128;
            int k = f >> 5, c = f & 31;
            Bt[c][k] = W[(size_t)(k0 + k) * SRANK + c];
        }
        __syncthreads();
#pragma unroll
        for (int kq = 0; kq < 8; kq++) {
            float4 a[4], bb[4];
#pragma unroll
            for (int i = 0; i < 4; i++) a[i]  = *(float4*)&As[ty + 16 * i][kq * 4];
#pragma unroll
            for (int j = 0; j < 4; j++) bb[j] = *(float4*)&Bt[tx + 8 * j][kq * 4];
#pragma unroll
            for (int i = 0; i < 4; i++)
#pragma unroll
                for (int j = 0; j < 4; j++) {
                    acc[i][j] += a[i].x * bb[j].x + a[i].y * bb[j].y
                               + a[i].z * bb[j].z + a[i].w * bb[j].w;
                }
        }
        __syncthreads();
    }
#pragma unroll
    for (int i = 0; i < 4; i++)
#pragma unroll
        for (int j = 0; j < 4; j++)
            C[(size_t)(rowBase + ty + 16 * i) * SRANK + tx + 8 * j] = acc[i][j];
}

// ---------------- GEMM2: C_z[4096,1024] = T[z][4096,32] * W_z[32,1024] -------
__global__ void __launch_bounds__(256)
gemm2_kernel(const float* __restrict__ T, const float* __restrict__ W0,
             const float* __restrict__ W1, const float* __restrict__ W2,
             float* __restrict__ C0, float* __restrict__ C1, float* __restrict__ C2) {
    __shared__ float As[64][36];
    __shared__ float Bt[64][36];
    int tid = threadIdx.x;
    int tx = tid & 15, ty = tid >> 4;
    int z = blockIdx.z;
    const float* W = (z == 0) ? W0 : (z == 1) ? W1 : W2;
    float* C = (z == 0) ? C0 : (z == 1) ? C1 : C2;
    const float* A = T + (size_t)z * NTOK * SRANK;
    int rowBase = blockIdx.x * 64, colBase = blockIdx.y * 64;

#pragma unroll
    for (int i = 0; i < 2; i++) {               // A: 64x32 = 512 float4
        int f = tid + i * 256;
        int r = f >> 3, kq = f & 7;
        float4 v = *(const float4*)(A + (size_t)(rowBase + r) * SRANK + kq * 4);
        *(float4*)&As[r][kq * 4] = v;
    }
#pragma unroll
    for (int i = 0; i < 8; i++) {               // B transposed: 64 cols x 32 k
        int f = tid + i * 256;
        int k = f >> 6, c = f & 63;
        Bt[c][k] = W[(size_t)k * D_MODEL + colBase + c];
    }
    __syncthreads();

    float acc[4][4];
#pragma unroll
    for (int i = 0; i < 4; i++)
#pragma unroll
        for (int j = 0; j < 4; j++) acc[i][j] = 0.f;
#pragma unroll
    for (int kq = 0; kq < 8; kq++) {
        float4 a[4], bb[4];
#pragma unroll
        for (int i = 0; i < 4; i++) a[i]  = *(float4*)&As[ty + 16 * i][kq * 4];
#pragma unroll
        for (int j = 0; j < 4; j++) bb[j] = *(float4*)&Bt[tx + 16 * j][kq * 4];
#pragma unroll
        for (int i = 0; i < 4; i++)
#pragma unroll
            for (int j = 0; j < 4; j++)
                acc[i][j] += a[i].x * bb[j].x + a[i].y * bb[j].y
                           + a[i].z * bb[j].z + a[i].w * bb[j].w;
    }
#pragma unroll
    for (int i = 0; i < 4; i++)
#pragma unroll
        for (int j = 0; j < 4; j++)
            C[(size_t)(rowBase + ty + 16 * i) * D_MODEL + colBase + tx + 16 * j] = acc[i][j];
}

// -------- adapters (up to 3 projections per block, sharing the x load) -------
struct AdpArgs {
    const float* ri[3];
    const float* ro[3];
    const float* lg[3];
    float*       base[3];
    int nproj;
    int ropemask;
};

__global__ void __launch_bounds__(128)
adapter_kernel(const float* __restrict__ X, const int* __restrict__ rules, AdpArgs A) {
    __shared__ float xs[D_MODEL];
    __shared__ float ris[HD * RANK];
    __shared__ float ros[RANK * HD];
    __shared__ float hs[NBLK * RANK];
    __shared__ float sels[NBLK];
    int n = blockIdx.x;
    int t = threadIdx.x;
    int rule = rules[n];

    const float4* x4 = (const float4*)(X + (size_t)n * D_MODEL);
    float4* xs4 = (float4*)xs;
    xs4[t] = x4[t];
    xs4[t + 128] = x4[t + 128];

    int spos = n & (S_LEN - 1);

    for (int p = 0; p < A.nproj; p++) {
#pragma unroll
        for (int i = 0; i < 4; i++) {
            ris[t + i * 128] = A.ri[p][rule * 512 + t + i * 128];
            ros[t + i * 128] = A.ro[p][rule * 512 + t + i * 128];
        }
        if (t < 32) {
            int j = t & 15;
            float v = A.lg[p][rule * NBLK + j] * 4.0f;
            float mx = v;
#pragma unroll
            for (int msk = 8; msk >= 1; msk >>= 1)
                mx = fmaxf(mx, __shfl_xor_sync(0xffffffffu, mx, msk));
            float e = expf(v - mx);
            float sm2 = e;
#pragma unroll
            for (int msk = 8; msk >= 1; msk >>= 1)
                sm2 += __shfl_xor_sync(0xffffffffu, sm2, msk);
            if (t < 16) sels[t] = e / sm2;
        }
        __syncthreads();
        {
            int blk = t >> 3, r = t & 7;
            float sum = 0.f;
#pragma unroll
            for (int sx = 0; sx < 64; sx++) sum += xs[blk * 64 + sx] * ris[sx * 8 + r];
            hs[t] = sum;
        }
        __syncthreads();
        int d0 = t * 8;
        int blk = t >> 3;
        float hl[8];
#pragma unroll
        for (int r = 0; r < 8; r++) hl[r] = hs[blk * 8 + r];
        float selv = sels[blk];
        float* Base = A.base[p];
        float outv[8];
#pragma unroll
        for (int c = 0; c < 8; c++) {
            int dh = (d0 + c) & 63;
            float a = 0.f;
#pragma unroll
            for (int r = 0; r < 8; r++) a += hl[r] * ros[r * 64 + dh];
            outv[c] = Base[(size_t)n * D_MODEL + d0 + c] + a * selv;
        }
        if ((A.ropemask >> p) & 1) {
#pragma unroll
            for (int pp = 0; pp < 4; pp++) {
                int dh = (d0 + 2 * pp) & 63;
                int i = dh >> 1;
                float div = expf((float)(2 * i) * (-0.14391156831212786f));
                float ang = (float)spos * div;
                float sn, cs;
                sincosf(ang, &sn, &cs);
                float t1 = outv[2 * pp], t2 = outv[2 * pp + 1];
                outv[2 * pp]     = t1 * cs - t2 * sn;
                outv[2 * pp + 1] = t2 * cs + t1 * sn;
            }
        }
#pragma unroll
        for (int c = 0; c < 8; c++) Base[(size_t)n * D_MODEL + d0 + c] = outv[c];
        __syncthreads();
    }
}

// ------------------------- flash attention (tf32 MMA) ------------------------
// CTA: 128 threads (4 warps). Warp w owns q-rows [16w, 16w+16) of the 64-row
// q-tile. smem strides chosen conflict-free for the fragment access patterns.
#define QS_STR 68
#define VS_STR 72
#define FLASH_SMEM ((2 * 64 * QS_STR + 64 * VS_STR) * 4 + 64 * 4)

__global__ void __launch_bounds__(128)
flash_tc(const float* __restrict__ Q, const float* __restrict__ K,
         const float* __restrict__ V, const int* __restrict__ rules,
         const unsigned long long* __restrict__ allow, float* __restrict__ O) {
    extern __shared__ float sm[];
    float* qs = sm;                       // [64][68], reused as ps after Q-frag extract
    float* ks = sm + 64 * QS_STR;         // [64][68]
    float* vs = ks + 64 * QS_STR;         // [64(d)][72]  (V transposed: vs[d][key])
    int*   rk_s = (int*)(vs + 64 * VS_STR);

    const int tid  = threadIdx.x;
    const int warp = tid >> 5, lane = tid & 31;
    const int g = lane >> 2, tq = lane & 3;
    const int qt = gridDim.x - 1 - blockIdx.x;     // heavy blocks first
    const int b = blockIdx.y >> 4, h = blockIdx.y & 15;
    const int tokBase = b * S_LEN;
    const int rbase = warp * 16;

    // ---- load Q tile, convert to tf32 ----
#pragma unroll
    for (int i = 0; i < 8; i++) {
        int f = tid + i * 128;
        int r = f >> 4, c4 = (f & 15) * 4;
        float4 v = *(const float4*)(Q + (size_t)(tokBase + qt * 64 + r) * D_MODEL + h * 64 + c4);
        float4 tv;
        tv.x = __uint_as_float(f2tf(v.x)); tv.y = __uint_as_float(f2tf(v.y));
        tv.z = __uint_as_float(f2tf(v.z)); tv.w = __uint_as_float(f2tf(v.w));
        *(float4*)(qs + r * QS_STR + c4) = tv;
    }
    __syncthreads();

    // ---- extract Q A-fragments (resident in registers) ----
    unsigned qa[8][4];
#pragma unroll
    for (int kk = 0; kk < 8; kk++) {
        qa[kk][0] = __float_as_uint(qs[(rbase + g) * QS_STR + kk * 8 + tq]);
        qa[kk][1] = __float_as_uint(qs[(rbase + g + 8) * QS_STR + kk * 8 + tq]);
        qa[kk][2] = __float_as_uint(qs[(rbase + g) * QS_STR + kk * 8 + tq + 4]);
        qa[kk][3] = __float_as_uint(qs[(rbase + g + 8) * QS_STR + kk * 8 + tq + 4]);
    }
    float* ps = qs;                        // recycled (per-warp rows only)

    const int qrow0 = qt * 64 + rbase + g;
    const int qrow1 = qrow0 + 8;
    const unsigned long long al0 = allow[b * S_LEN + qrow0];
    const unsigned long long al1 = allow[b * S_LEN + qrow1];

    float o[8][4];
#pragma unroll
    for (int nt = 0; nt < 8; nt++)
#pragma unroll
        for (int j = 0; j < 4; j++) o[nt][j] = 0.f;
    float m0 = NEGINF, m1 = NEGINF, l0 = 0.f, l1 = 0.f;

    for (int kt = 0; kt <= qt; kt++) {
        __syncthreads();                    // protect prior-iteration ks/vs reads
#pragma unroll
        for (int i = 0; i < 8; i++) {
            int f = tid + i * 128;
            int r = f >> 4, c4 = (f & 15) * 4;
            size_t go = (size_t)(tokBase + kt * 64 + r) * D_MODEL + h * 64 + c4;
            float4 kv = *(const float4*)(K + go);
            float4 tk;
            tk.x = __uint_as_float(f2tf(kv.x)); tk.y = __uint_as_float(f2tf(kv.y));
            tk.z = __uint_as_float(f2tf(kv.z)); tk.w = __uint_as_float(f2tf(kv.w));
            *(float4*)(ks + r * QS_STR + c4) = tk;
            float4 vv = *(const float4*)(V + go);
            vs[(c4 + 0) * VS_STR + r] = __uint_as_float(f2tf(vv.x));
            vs[(c4 + 1) * VS_STR + r] = __uint_as_float(f2tf(vv.y));
            vs[(c4 + 2) * VS_STR + r] = __uint_as_float(f2tf(vv.z));
            vs[(c4 + 3) * VS_STR + r] = __uint_as_float(f2tf(vv.w));
        }
        if (tid < 64) rk_s[tid] = rules[tokBase + kt * 64 + tid];
        __syncthreads();

        // ---- S = Q K^T ----
        float s[8][4];
#pragma unroll
        for (int nt = 0; nt < 8; nt++)
#pragma unroll
            for (int j = 0; j < 4; j++) s[nt][j] = 0.f;
#pragma unroll
        for (int kk = 0; kk < 8; kk++) {
#pragma unroll
            for (int nt = 0; nt < 8; nt++) {
                unsigned b0 = __float_as_uint(ks[(nt * 8 + g) * QS_STR + kk * 8 + tq]);
                unsigned b1 = __float_as_uint(ks[(nt * 8 + g) * QS_STR + kk * 8 + tq + 4]);
                mma_tf32(s[nt], qa[kk], b0, b1);
            }
        }

        // ---- mask + scale ----
        const bool diag = (kt == qt);
#pragma unroll
        for (int nt = 0; nt < 8; nt++) {
            int c0 = nt * 8 + 2 * tq;
            int rk0 = rk_s[c0], rk1 = rk_s[c0 + 1];
            int col0 = kt * 64 + c0;
            bool ok00 = ((al0 >> rk0) & 1ULL) && (!diag || col0 <= qrow0);
            bool ok01 = ((al0 >> rk1) & 1ULL) && (!diag || col0 + 1 <= qrow0);
            bool ok10 = ((al1 >> rk0) & 1ULL) && (!diag || col0 <= qrow1);
            bool ok11 = ((al1 >> rk1) & 1ULL) && (!diag || col0 + 1 <= qrow1);
            s[nt][0] = ok00 ? s[nt][0] * 0.125f : NEGINF;
            s[nt][1] = ok01 ? s[nt][1] * 0.125f : NEGINF;
            s[nt][2] = ok10 ? s[nt][2] * 0.125f : NEGINF;
            s[nt][3] = ok11 ? s[nt][3] * 0.125f : NEGINF;
        }

        // ---- online softmax (rows g and g+8) ----
        float mx0 = NEGINF, mx1 = NEGINF;
#pragma unroll
        for (int nt = 0; nt < 8; nt++) {
            mx0 = fmaxf(mx0, fmaxf(s[nt][0], s[nt][1]));
            mx1 = fmaxf(mx1, fmaxf(s[nt][2], s[nt][3]));
        }
        mx0 = fmaxf(mx0, __shfl_xor_sync(0xffffffffu, mx0, 1));
        mx0 = fmaxf(mx0, __shfl_xor_sync(0xffffffffu, mx0, 2));
        mx1 = fmaxf(mx1, __shfl_xor_sync(0xffffffffu, mx1, 1));
        mx1 = fmaxf(mx1, __shfl_xor_sync(0xffffffffu, mx1, 2));
        float mn0 = fmaxf(m0, mx0), mn1 = fmaxf(m1, mx1);
        float cr0 = (m0 == mn0) ? 1.f : __expf(m0 - mn0);
        float cr1 = (m1 == mn1) ? 1.f : __expf(m1 - mn1);
        float rs0 = 0.f, rs1 = 0.f;
        if (mn0 != NEGINF) {
#pragma unroll
            for (int nt = 0; nt < 8; nt++) {
                s[nt][0] = __expf(s[nt][0] - mn0);
                s[nt][1] = __expf(s[nt][1] - mn0);
                rs0 += s[nt][0] + s[nt][1];
            }
        } else {
#pragma unroll
            for (int nt = 0; nt < 8; nt++) { s[nt][0] = 0.f; s[nt][1] = 0.f; }
        }
        if (mn1 != NEGINF) {
#pragma unroll
            for (int nt = 0; nt < 8; nt++) {
                s[nt][2] = __expf(s[nt][2] - mn1);
                s[nt][3] = __expf(s[nt][3] - mn1);
                rs1 += s[nt][2] + s[nt][3];
            }
        } else {
#pragma unroll
            for (int nt = 0; nt < 8; nt++) { s[nt][2] = 0.f; s[nt][3] = 0.f; }
        }
        rs0 += __shfl_xor_sync(0xffffffffu, rs0, 1);
        rs0 += __shfl_xor_sync(0xffffffffu, rs0, 2);
        rs1 += __shfl_xor_sync(0xffffffffu, rs1, 1);
        rs1 += __shfl_xor_sync(0xffffffffu, rs1, 2);
        l0 = l0 * cr0 + rs0;
        l1 = l1 * cr1 + rs1;
        m0 = mn0; m1 = mn1;
#pragma unroll
        for (int nt = 0; nt < 8; nt++) {
            o[nt][0] *= cr0; o[nt][1] *= cr0;
            o[nt][2] *= cr1; o[nt][3] *= cr1;
        }

        // ---- stage P (tf32) into per-warp smem ----
#pragma unroll
        for (int nt = 0; nt < 8; nt++) {
            uint2 u0 = make_uint2(f2tf(s[nt][0]), f2tf(s[nt][1]));
            uint2 u1 = make_uint2(f2tf(s[nt][2]), f2tf(s[nt][3]));
            *(uint2*)(ps + (rbase + g) * QS_STR + nt * 8 + 2 * tq) = u0;
            *(uint2*)(ps + (rbase + g + 8) * QS_STR + nt * 8 + 2 * tq) = u1;
        }
        __syncwarp();

        // ---- O += P V ----
#pragma unroll
        for (int kk = 0; kk < 8; kk++) {
            unsigned pa[4];
            pa[0] = __float_as_uint(ps[(rbase + g) * QS_STR + kk * 8 + tq]);
            pa[1] = __float_as_uint(ps[(rbase + g + 8) * QS_STR + kk * 8 + tq]);
            pa[2] = __float_as_uint(ps[(rbase + g) * QS_STR + kk * 8 + tq + 4]);
            pa[3] = __float_as_uint(ps[(rbase + g + 8) * QS_STR + kk * 8 + tq + 4]);
#pragma unroll
            for (int nt = 0; nt < 8; nt++) {
                unsigned b0 = __float_as_uint(vs[(nt * 8 + g) * VS_STR + kk * 8 + tq]);
                unsigned b1 = __float_as_uint(vs[(nt * 8 + g) * VS_STR + kk * 8 + tq + 4]);
                mma_tf32(o[nt], pa, b0, b1);
            }
        }
        __syncwarp();
    }

    float inv0 = 1.f / l0, inv1 = 1.f / l1;
#pragma unroll
    for (int nt = 0; nt < 8; nt++) {
        float2 w0 = make_float2(o[nt][0] * inv0, o[nt][1] * inv0);
        float2 w1 = make_float2(o[nt][2] * inv1, o[nt][3] * inv1);
        *(float2*)(O + (size_t)(tokBase + qrow0) * D_MODEL + h * 64 + nt * 8 + 2 * tq) = w0;
        *(float2*)(O + (size_t)(tokBase + qrow1) * D_MODEL + h * 64 + nt * 8 + 2 * tq) = w1;
    }
}

// ----------------------------------------------------------------------------
extern "C" void kernel_launch(void* const* d_in, const int* in_sizes, int n_in,
                              void* d_out, int out_size) {
    const float* x     = (const float*)d_in[0];
    const int*   rules = (const int*)  d_in[1];
    const float* q_si = (const float*)d_in[2],  *q_so = (const float*)d_in[3];
    const float* q_ri = (const float*)d_in[4],  *q_ro = (const float*)d_in[5];
    const float* q_lg = (const float*)d_in[6];
    const float* k_si = (const float*)d_in[7],  *k_so = (const float*)d_in[8];
    const float* k_ri = (const float*)d_in[9],  *k_ro = (const float*)d_in[10];
    const float* k_lg = (const float*)d_in[11];
    const float* v_si = (const float*)d_in[12], *v_so = (const float*)d_in[13];
    const float* v_ri = (const float*)d_in[14], *v_ro = (const float*)d_in[15];
    const float* v_lg = (const float*)d_in[16];
    const float* o_si = (const float*)d_in[17], *o_so = (const float*)d_in[18];
    const float* o_ri = (const float*)d_in[19], *o_ro = (const float*)d_in[20];
    const float* o_lg = (const float*)d_in[21];
    const float* router_q = (const float*)d_in[22];
    const float* router_k = (const float*)d_in[23];
    float* out = (float*)d_out;

    float *T1, *Qb, *Kb, *Vb, *AO, *Atab;
    unsigned long long* Allow;
    cudaGetSymbolAddress((void**)&T1,    g_T1);
    cudaGetSymbolAddress((void**)&Qb,    g_Q);
    cudaGetSymbolAddress((void**)&Kb,    g_K);
    cudaGetSymbolAddress((void**)&Vb,    g_V);
    cudaGetSymbolAddress((void**)&AO,    g_AO);
    cudaGetSymbolAddress((void**)&Atab,  g_A);
    cudaGetSymbolAddress((void**)&Allow, g_allow);

    aff_kernel<<<16, 256>>>(router_q, router_k, Atab);
    thr_allow_kernel<<<NTOK, 64>>>(rules, Atab, Allow);

    // QKV base projections (batched z=3)
    gemm1_kernel<<<dim3(64, 1, 3), 128>>>(x, q_si, k_si, v_si, T1);
    gemm2_kernel<<<dim3(64, 16, 3), 256>>>(T1, q_so, k_so, v_so, Qb, Kb, Vb);

    AdpArgs aq;
    aq.ri[0] = q_ri; aq.ri[1] = k_ri; aq.ri[2] = v_ri;
    aq.ro[0] = q_ro; aq.ro[1] = k_ro; aq.ro[2] = v_ro;
    aq.lg[0] = q_lg; aq.lg[1] = k_lg; aq.lg[2] = v_lg;
    aq.base[0] = Qb; aq.base[1] = Kb; aq.base[2] = Vb;
    aq.nproj = 3; aq.ropemask = 0x3;       // rope on q,k
    adapter_kernel<<<NTOK, 128>>>(x, rules, aq);

    // flash attention (tf32 tensor cores)
    cudaFuncSetAttribute(flash_tc, cudaFuncAttributeMaxDynamicSharedMemorySize, FLASH_SMEM);
    flash_tc<<<dim3(16, 64), 128, FLASH_SMEM>>>(Qb, Kb, Vb, rules, Allow, AO);

    // O projection
    gemm1_kernel<<<dim3(64, 1, 1), 128>>>(AO, o_si, o_si, o_si, T1);
    gemm2_kernel<<<dim3(64, 16, 1), 256>>>(T1, o_so, o_so, o_so, out, out, out);

    AdpArgs ao;
    ao.ri[0] = o_ri; ao.ri[1] = o_ri; ao.ri[2] = o_ri;
    ao.ro[0] = o_ro; ao.ro[1] = o_ro; ao.ro[2] = o_ro;
    ao.lg[0] = o_lg; ao.lg[1] = o_lg; ao.lg[2] = o_lg;
    ao.base[0] = out; ao.base[1] = out; ao.base[2] = out;
    ao.nproj = 1; ao.ropemask = 0;
    adapter_kernel<<<NTOK, 128>>>(AO, rules, ao);
}

// round 3
// speedup vs baseline: 1.8047x; 1.1013x over previous
#include <cuda_runtime.h>
#include <math.h>

#define D_MODEL 1024
#define S_LEN   1024
#define BATCH   4
#define NTOK    4096
#define NHEADS  16
#define HD      64
#define NRULES  64
#define RANK    8
#define SRANK   32
#define NBLK    16
#define TOPK    32

#define NEGINF (__int_as_float(0xff800000))

// ---------------- scratch (device globals; no allocation allowed) ------------
__device__ float g_T1[3 * NTOK * SRANK];
__device__ float g_Q [NTOK * D_MODEL];
__device__ float g_K [NTOK * D_MODEL];
__device__ float g_V [NTOK * D_MODEL];
__device__ float g_AO[NTOK * D_MODEL];
__device__ float g_A [NRULES * NRULES];
__device__ unsigned long long g_allow[NTOK];
__device__ float2 g_rope[S_LEN * 32];

__device__ __forceinline__ unsigned f2tf(float x) {
    unsigned u;
    asm("cvt.rna.tf32.f32 %0, %1;" : "=r"(u) : "f"(x));
    return u;
}

__device__ __forceinline__ void mma_tf32(float d[4], const unsigned a[4],
                                         unsigned b0, unsigned b1) {
    asm volatile(
        "mma.sync.aligned.m16n8k8.row.col.f32.tf32.tf32.f32 "
        "{%0,%1,%2,%3}, {%4,%5,%6,%7}, {%8,%9}, {%0,%1,%2,%3};\n"
        : "+f"(d[0]), "+f"(d[1]), "+f"(d[2]), "+f"(d[3])
        : "r"(a[0]), "r"(a[1]), "r"(a[2]), "r"(a[3]), "r"(b0), "r"(b1));
}

__device__ __forceinline__ void cp16(float* smem_dst, const float* gsrc) {
    unsigned s = (unsigned)__cvta_generic_to_shared(smem_dst);
    asm volatile("cp.async.cg.shared.global [%0], [%1], 16;" :: "r"(s), "l"(gsrc));
}
__device__ __forceinline__ void cp_commit() {
    asm volatile("cp.async.commit_group;");
}
template <int N>
__device__ __forceinline__ void cp_wait() {
    asm volatile("cp.async.wait_group %0;" :: "n"(N));
}

// ---------------- affinity table ---------------------------------------------
__global__ void aff_kernel(const float* __restrict__ rq, const float* __restrict__ rk,
                           float* __restrict__ A) {
    int idx = blockIdx.x * blockDim.x + threadIdx.x;
    if (idx >= NRULES * NRULES) return;
    int i = idx >> 6, j = idx & 63;
    float qv[RANK], kv[RANK];
    float nq = 0.f, nk = 0.f;
#pragma unroll
    for (int r = 0; r < RANK; r++) {
        qv[r] = rq[i * RANK + r]; kv[r] = rk[j * RANK + r];
        nq += qv[r] * qv[r];      nk += kv[r] * kv[r];
    }
    float iq = 1.f / fmaxf(sqrtf(nq), 1e-12f);
    float ik = 1.f / fmaxf(sqrtf(nk), 1e-12f);
    float dot = 0.f;
#pragma unroll
    for (int r = 0; r < RANK; r++) dot += (qv[r] * iq) * (kv[r] * ik);
    A[idx] = dot * 2.0794415416798357f;
}

// ---------------- rope table --------------------------------------------------
__global__ void rope_kernel(float2* __restrict__ tab) {
    int idx = blockIdx.x * blockDim.x + threadIdx.x;
    if (idx >= S_LEN * 32) return;
    int spos = idx >> 5, i = idx & 31;
    float div = expf((float)(2 * i) * (-0.14391156831212786f)); // -ln(1e4)/64
    float ang = (float)spos * div;
    float sn, cs;
    sincosf(ang, &sn, &cs);
    tab[idx] = make_float2(cs, sn);
}

// --------- per-(b,q): top-32 threshold + allowed-rule 64-bit mask ------------
__global__ void thr_allow_kernel(const int* __restrict__ rules, const float* __restrict__ A,
                                 unsigned long long* __restrict__ allow) {
    int bq = blockIdx.x;
    int b = bq >> 10, q = bq & 1023;
    __shared__ int   cnt[NRULES];
    __shared__ float row[NRULES];
    __shared__ float thr_s;
    __shared__ unsigned bits[2];
    int t = threadIdx.x;      // 64 threads
    cnt[t] = 0;
    if (t == 0) thr_s = NEGINF;
    __syncthreads();
    const int* rb = rules + b * S_LEN;
    for (int k = t; k <= q; k += 64) atomicAdd(&cnt[rb[k]], 1);
    row[t] = A[rb[q] * NRULES + t];
    __syncthreads();
    if (q >= TOPK - 1) {
        float v = row[t];
        int   c = cnt[t];
        int greater = 0;
#pragma unroll 8
        for (int r = 0; r < NRULES; r++) greater += (row[r] > v) ? cnt[r] : 0;
        if (c > 0 && greater < TOPK && greater + c >= TOPK)
            thr_s = v;
    }
    __syncthreads();
    unsigned bal = __ballot_sync(0xffffffffu, row[t] >= thr_s);
    if ((t & 31) == 0) bits[t >> 5] = bal;
    __syncthreads();
    if (t == 0)
        allow[bq] = (unsigned long long)bits[0] | ((unsigned long long)bits[1] << 32);
}

// ---------------- GEMM1: T[z][4096,32] = X[4096,1024] * W_z[1024,32] ---------
__global__ void __launch_bounds__(128)
gemm1_kernel(const float* __restrict__ X, const float* __restrict__ W0,
             const float* __restrict__ W1, const float* __restrict__ W2,
             float* __restrict__ T) {
    __shared__ float As[32][36];
    __shared__ float Bt[32][36];
    int tid = threadIdx.x;
    int tx = tid & 7, ty = tid >> 3;       // tx: col/4 (8), ty: row (16)
    int z = blockIdx.z;
    const float* W = (z == 0) ? W0 : (z == 1) ? W1 : W2;
    float* C = T + (size_t)z * NTOK * SRANK;
    int rowBase = blockIdx.x * 32;
    float acc[2][4];
#pragma unroll
    for (int i = 0; i < 2; i++)
#pragma unroll
        for (int j = 0; j < 4; j++) acc[i][j] = 0.f;

    for (int k0 = 0; k0 < D_MODEL; k0 += 32) {
#pragma unroll
        for (int i = 0; i < 2; i++) {            // A: 32x32 = 256 float4
            int f = tid + i * 128;
            int r = f >> 3, kq = f & 7;
            float4 v = *(const float4*)(X + (size_t)(rowBase + r) * D_MODEL + k0 + kq * 4);
            *(float4*)&As[r][kq * 4] = v;
        }
#pragma unroll
        for (int i = 0; i < 8; i++) {            // B transposed: 32x32
            int f = tid + i * 128;
            int k = f >> 5, c = f & 31;
            Bt[c][k] = W[(size_t)(k0 + k) * SRANK + c];
        }
        __syncthreads();
#pragma unroll
        for (int kq = 0; kq < 8; kq++) {
            float4 a[2], bb[4];
#pragma unroll
            for (int i = 0; i < 2; i++) a[i]  = *(float4*)&As[ty + 16 * i][kq * 4];
#pragma unroll
            for (int j = 0; j < 4; j++) bb[j] = *(float4*)&Bt[tx + 8 * j][kq * 4];
#pragma unroll
            for (int i = 0; i < 2; i++)
#pragma unroll
                for (int j = 0; j < 4; j++)
                    acc[i][j] += a[i].x * bb[j].x + a[i].y * bb[j].y
                               + a[i].z * bb[j].z + a[i].w * bb[j].w;
        }
        __syncthreads();
    }
#pragma unroll
    for (int i = 0; i < 2; i++)
#pragma unroll
        for (int j = 0; j < 4; j++)
            C[(size_t)(rowBase + ty + 16 * i) * SRANK + tx + 8 * j] = acc[i][j];
}

// ---------------- GEMM2: C_z[4096,1024] = T[z][4096,32] * W_z[32,1024] -------
__global__ void __launch_bounds__(256)
gemm2_kernel(const float* __restrict__ T, const float* __restrict__ W0,
             const float* __restrict__ W1, const float* __restrict__ W2,
             float* __restrict__ C0, float* __restrict__ C1, float* __restrict__ C2) {
    __shared__ float As[64][36];
    __shared__ float Bt[64][36];
    int tid = threadIdx.x;
    int tx = tid & 15, ty = tid >> 4;
    int z = blockIdx.z;
    const float* W = (z == 0) ? W0 : (z == 1) ? W1 : W2;
    float* C = (z == 0) ? C0 : (z == 1) ? C1 : C2;
    const float* A = T + (size_t)z * NTOK * SRANK;
    int rowBase = blockIdx.x * 64, colBase = blockIdx.y * 64;

#pragma unroll
    for (int i = 0; i < 2; i++) {
        int f = tid + i * 256;
        int r = f >> 3, kq = f & 7;
        float4 v = *(const float4*)(A + (size_t)(rowBase + r) * SRANK + kq * 4);
        *(float4*)&As[r][kq * 4] = v;
    }
#pragma unroll
    for (int i = 0; i < 8; i++) {
        int f = tid + i * 256;
        int k = f >> 6, c = f & 63;
        Bt[c][k] = W[(size_t)k * D_MODEL + colBase + c];
    }
    __syncthreads();

    float acc[4][4];
#pragma unroll
    for (int i = 0; i < 4; i++)
#pragma unroll
        for (int j = 0; j < 4; j++) acc[i][j] = 0.f;
#pragma unroll
    for (int kq = 0; kq < 8; kq++) {
        float4 a[4], bb[4];
#pragma unroll
        for (int i = 0; i < 4; i++) a[i]  = *(float4*)&As[ty + 16 * i][kq * 4];
#pragma unroll
        for (int j = 0; j < 4; j++) bb[j] = *(float4*)&Bt[tx + 16 * j][kq * 4];
#pragma unroll
        for (int i = 0; i < 4; i++)
#pragma unroll
            for (int j = 0; j < 4; j++)
                acc[i][j] += a[i].x * bb[j].x + a[i].y * bb[j].y
                           + a[i].z * bb[j].z + a[i].w * bb[j].w;
    }
#pragma unroll
    for (int i = 0; i < 4; i++)
#pragma unroll
        for (int j = 0; j < 4; j++)
            C[(size_t)(rowBase + ty + 16 * i) * D_MODEL + colBase + tx + 16 * j] = acc[i][j];
}

// -------- adapters (up to 3 projections per block, sharing the x load) -------
struct AdpArgs {
    const float* ri[3];
    const float* ro[3];
    const float* lg[3];
    float*       base[3];
    int nproj;
    int ropemask;
    int tfmask;      // projections whose output should be tf32-rounded
};

__global__ void __launch_bounds__(128)
adapter_kernel(const float* __restrict__ X, const int* __restrict__ rules,
               const float2* __restrict__ rope, AdpArgs A) {
    __shared__ float xs[D_MODEL];
    __shared__ float ris[HD * RANK];
    __shared__ float ros[RANK * HD];
    __shared__ float hs[NBLK * RANK];
    __shared__ float sels[NBLK];
    int n = blockIdx.x;
    int t = threadIdx.x;
    int rule = rules[n];

    const float4* x4 = (const float4*)(X + (size_t)n * D_MODEL);
    float4* xs4 = (float4*)xs;
    xs4[t] = x4[t];
    xs4[t + 128] = x4[t + 128];

    int spos = n & (S_LEN - 1);

    for (int p = 0; p < A.nproj; p++) {
#pragma unroll
        for (int i = 0; i < 4; i++) {
            ris[t + i * 128] = A.ri[p][rule * 512 + t + i * 128];
            ros[t + i * 128] = A.ro[p][rule * 512 + t + i * 128];
        }
        if (t < 32) {
            int j = t & 15;
            float v = A.lg[p][rule * NBLK + j] * 4.0f;
            float mx = v;
#pragma unroll
            for (int msk = 8; msk >= 1; msk >>= 1)
                mx = fmaxf(mx, __shfl_xor_sync(0xffffffffu, mx, msk));
            float e = expf(v - mx);
            float sm2 = e;
#pragma unroll
            for (int msk = 8; msk >= 1; msk >>= 1)
                sm2 += __shfl_xor_sync(0xffffffffu, sm2, msk);
            if (t < 16) sels[t] = e / sm2;
        }
        __syncthreads();
        {
            int blk = t >> 3, r = t & 7;
            float sum = 0.f;
#pragma unroll
            for (int sx = 0; sx < 64; sx++) sum += xs[blk * 64 + sx] * ris[sx * 8 + r];
            hs[t] = sum;
        }
        __syncthreads();
        int d0 = t * 8;
        int blk = t >> 3;
        float hl[8];
#pragma unroll
        for (int r = 0; r < 8; r++) hl[r] = hs[blk * 8 + r];
        float selv = sels[blk];
        float* Base = A.base[p];
        float outv[8];
#pragma unroll
        for (int c = 0; c < 8; c++) {
            int dh = (d0 + c) & 63;
            float a = 0.f;
#pragma unroll
            for (int r = 0; r < 8; r++) a += hl[r] * ros[r * 64 + dh];
            outv[c] = Base[(size_t)n * D_MODEL + d0 + c] + a * selv;
        }
        if ((A.ropemask >> p) & 1) {
#pragma unroll
            for (int pp = 0; pp < 4; pp++) {
                int dh = (d0 + 2 * pp) & 63;
                int i = dh >> 1;
                float2 cs = __ldg(&rope[spos * 32 + i]);
                float t1 = outv[2 * pp], t2 = outv[2 * pp + 1];
                outv[2 * pp]     = t1 * cs.x - t2 * cs.y;
                outv[2 * pp + 1] = t2 * cs.x + t1 * cs.y;
            }
        }
        if ((A.tfmask >> p) & 1) {
#pragma unroll
            for (int c = 0; c < 8; c++) outv[c] = __uint_as_float(f2tf(outv[c]));
        }
#pragma unroll
        for (int c = 0; c < 8; c++) Base[(size_t)n * D_MODEL + d0 + c] = outv[c];
        __syncthreads();
    }
}

// ------------------------- flash attention (tf32 MMA) ------------------------
// Q/K/V in gmem are already tf32-rounded (adapter epilogue). K/V tiles are
// copied verbatim with cp.async, double-buffered. V stored untransposed with
// stride 72 (conflict-free B-frag reads). P fragments via quad shuffles.
#define QS_STR 68
#define VS_STR 72
#define FLASH_SMEM ((3 * 64 * QS_STR + 2 * 64 * VS_STR + 128) * 4)

__global__ void __launch_bounds__(128)
flash_tc(const float* __restrict__ Q, const float* __restrict__ K,
         const float* __restrict__ V, const int* __restrict__ rules,
         const unsigned long long* __restrict__ allow, float* __restrict__ O) {
    extern __shared__ float sm[];
    float* qs  = sm;                              // [64][68]
    float* ksb[2]; float* vsb[2]; int* rkb[2];
    ksb[0] = sm + 64 * QS_STR;
    ksb[1] = ksb[0] + 64 * QS_STR;
    vsb[0] = ksb[1] + 64 * QS_STR;
    vsb[1] = vsb[0] + 64 * VS_STR;
    rkb[0] = (int*)(vsb[1] + 64 * VS_STR);
    rkb[1] = rkb[0] + 64;

    const int tid  = threadIdx.x;
    const int warp = tid >> 5, lane = tid & 31;
    const int g = lane >> 2, tq = lane & 3;
    const int qt = gridDim.x - 1 - blockIdx.x;     // heavy blocks first
    const int b = blockIdx.y >> 4, h = blockIdx.y & 15;
    const int tokBase = b * S_LEN;
    const int rbase = warp * 16;

    const int ldr = tid >> 4, ldc = (tid & 15) * 4;

    // ---- issue async copy of tile 0 ----
    {
        float* ks = ksb[0]; float* vs = vsb[0];
#pragma unroll
        for (int i = 0; i < 8; i++) {
            int r = ldr + i * 8;
            size_t go = (size_t)(tokBase + r) * D_MODEL + h * 64 + ldc;
            cp16(ks + r * QS_STR + ldc, K + go);
            cp16(vs + r * VS_STR + ldc, V + go);
        }
        cp_commit();
        if (tid < 64) rkb[0][tid] = rules[tokBase + tid];
    }

    // ---- load Q tile (already tf32) ----
#pragma unroll
    for (int i = 0; i < 8; i++) {
        int r = ldr + i * 8;
        float4 v = *(const float4*)(Q + (size_t)(tokBase + qt * 64 + r) * D_MODEL + h * 64 + ldc);
        *(float4*)(qs + r * QS_STR + ldc) = v;
    }
    __syncthreads();

    unsigned qa[8][4];
#pragma unroll
    for (int kk = 0; kk < 8; kk++) {
        qa[kk][0] = __float_as_uint(qs[(rbase + g) * QS_STR + kk * 8 + tq]);
        qa[kk][1] = __float_as_uint(qs[(rbase + g + 8) * QS_STR + kk * 8 + tq]);
        qa[kk][2] = __float_as_uint(qs[(rbase + g) * QS_STR + kk * 8 + tq + 4]);
        qa[kk][3] = __float_as_uint(qs[(rbase + g + 8) * QS_STR + kk * 8 + tq + 4]);
    }

    const int qrow0 = qt * 64 + rbase + g;
    const int qrow1 = qrow0 + 8;
    const unsigned long long al0 = allow[b * S_LEN + qrow0];
    const unsigned long long al1 = allow[b * S_LEN + qrow1];

    float o[8][4];
#pragma unroll
    for (int nt = 0; nt < 8; nt++)
#pragma unroll
        for (int j = 0; j < 4; j++) o[nt][j] = 0.f;
    float m0 = NEGINF, m1 = NEGINF, l0 = 0.f, l1 = 0.f;

    for (int kt = 0; kt <= qt; kt++) {
        const int buf = kt & 1;
        __syncthreads();                 // prior compute done before refilling buf^1
        if (kt < qt) {
            float* ks = ksb[buf ^ 1]; float* vs = vsb[buf ^ 1];
#pragma unroll
            for (int i = 0; i < 8; i++) {
                int r = ldr + i * 8;
                size_t go = (size_t)(tokBase + (kt + 1) * 64 + r) * D_MODEL + h * 64 + ldc;
                cp16(ks + r * QS_STR + ldc, K + go);
                cp16(vs + r * VS_STR + ldc, V + go);
            }
            cp_commit();
            if (tid < 64) rkb[buf ^ 1][tid] = rules[tokBase + (kt + 1) * 64 + tid];
            cp_wait<1>();
        } else {
            cp_wait<0>();
        }
        __syncthreads();

        const float* ks = ksb[buf];
        const float* vs = vsb[buf];
        const int*   rk_s = rkb[buf];

        // ---- S = Q K^T ----
        float s[8][4];
#pragma unroll
        for (int nt = 0; nt < 8; nt++)
#pragma unroll
            for (int j = 0; j < 4; j++) s[nt][j] = 0.f;
#pragma unroll
        for (int kk = 0; kk < 8; kk++) {
#pragma unroll
            for (int nt = 0; nt < 8; nt++) {
                unsigned b0 = __float_as_uint(ks[(nt * 8 + g) * QS_STR + kk * 8 + tq]);
                unsigned b1 = __float_as_uint(ks[(nt * 8 + g) * QS_STR + kk * 8 + tq + 4]);
                mma_tf32(s[nt], qa[kk], b0, b1);
            }
        }

        // ---- mask + scale ----
        const bool diag = (kt == qt);
#pragma unroll
        for (int nt = 0; nt < 8; nt++) {
            int c0 = nt * 8 + 2 * tq;
            int rk0 = rk_s[c0], rk1 = rk_s[c0 + 1];
            int col0 = kt * 64 + c0;
            bool ok00 = ((al0 >> rk0) & 1ULL) && (!diag || col0 <= qrow0);
            bool ok01 = ((al0 >> rk1) & 1ULL) && (!diag || col0 + 1 <= qrow0);
            bool ok10 = ((al1 >> rk0) & 1ULL) && (!diag || col0 <= qrow1);
            bool ok11 = ((al1 >> rk1) & 1ULL) && (!diag || col0 + 1 <= qrow1);
            s[nt][0] = ok00 ? s[nt][0] * 0.125f : NEGINF;
            s[nt][1] = ok01 ? s[nt][1] * 0.125f : NEGINF;
            s[nt][2] = ok10 ? s[nt][2] * 0.125f : NEGINF;
            s[nt][3] = ok11 ? s[nt][3] * 0.125f : NEGINF;
        }

        // ---- online softmax ----
        float mx0 = NEGINF, mx1 = NEGINF;
#pragma unroll
        for (int nt = 0; nt < 8; nt++) {
            mx0 = fmaxf(mx0, fmaxf(s[nt][0], s[nt][1]));
            mx1 = fmaxf(mx1, fmaxf(s[nt][2], s[nt][3]));
        }
        mx0 = fmaxf(mx0, __shfl_xor_sync(0xffffffffu, mx0, 1));
        mx0 = fmaxf(mx0, __shfl_xor_sync(0xffffffffu, mx0, 2));
        mx1 = fmaxf(mx1, __shfl_xor_sync(0xffffffffu, mx1, 1));
        mx1 = fmaxf(mx1, __shfl_xor_sync(0xffffffffu, mx1, 2));
        float mn0 = fmaxf(m0, mx0), mn1 = fmaxf(m1, mx1);
        float cr0 = (m0 == mn0) ? 1.f : __expf(m0 - mn0);
        float cr1 = (m1 == mn1) ? 1.f : __expf(m1 - mn1);
        float rs0 = 0.f, rs1 = 0.f;
        if (mn0 != NEGINF) {
#pragma unroll
            for (int nt = 0; nt < 8; nt++) {
                s[nt][0] = __expf(s[nt][0] - mn0);
                s[nt][1] = __expf(s[nt][1] - mn0);
                rs0 += s[nt][0] + s[nt][1];
            }
        } else {
#pragma unroll
            for (int nt = 0; nt < 8; nt++) { s[nt][0] = 0.f; s[nt][1] = 0.f; }
        }
        if (mn1 != NEGINF) {
#pragma unroll
            for (int nt = 0; nt < 8; nt++) {
                s[nt][2] = __expf(s[nt][2] - mn1);
                s[nt][3] = __expf(s[nt][3] - mn1);
                rs1 += s[nt][2] + s[nt][3];
            }
        } else {
#pragma unroll
            for (int nt = 0; nt < 8; nt++) { s[nt][2] = 0.f; s[nt][3] = 0.f; }
        }
        rs0 += __shfl_xor_sync(0xffffffffu, rs0, 1);
        rs0 += __shfl_xor_sync(0xffffffffu, rs0, 2);
        rs1 += __shfl_xor_sync(0xffffffffu, rs1, 1);
        rs1 += __shfl_xor_sync(0xffffffffu, rs1, 2);
        l0 = l0 * cr0 + rs0;
        l1 = l1 * cr1 + rs1;
        m0 = mn0; m1 = mn1;
#pragma unroll
        for (int nt = 0; nt < 8; nt++) {
            o[nt][0] *= cr0; o[nt][1] *= cr0;
            o[nt][2] *= cr1; o[nt][3] *= cr1;
        }

        // ---- round P to tf32 (only used by MMA below) ----
#pragma unroll
        for (int nt = 0; nt < 8; nt++)
#pragma unroll
            for (int j = 0; j < 4; j++)
                s[nt][j] = __uint_as_float(f2tf(s[nt][j]));

        // ---- O += P V  (P fragments gathered via quad shuffles) ----
        const unsigned srcA = (lane & 28) | (tq >> 1);
        const unsigned srcB = srcA + 2;
        const bool odd = (tq & 1);
#pragma unroll
        for (int kk = 0; kk < 8; kk++) {
            float x0 = __shfl_sync(0xffffffffu, s[kk][0], srcA);
            float x1 = __shfl_sync(0xffffffffu, s[kk][1], srcA);
            float x2 = __shfl_sync(0xffffffffu, s[kk][2], srcA);
            float x3 = __shfl_sync(0xffffffffu, s[kk][3], srcA);
            float y0 = __shfl_sync(0xffffffffu, s[kk][0], srcB);
            float y1 = __shfl_sync(0xffffffffu, s[kk][1], srcB);
            float y2 = __shfl_sync(0xffffffffu, s[kk][2], srcB);
            float y3 = __shfl_sync(0xffffffffu, s[kk][3], srcB);
            unsigned pa[4];
            pa[0] = __float_as_uint(odd ? x1 : x0);
            pa[1] = __float_as_uint(odd ? x3 : x2);
            pa[2] = __float_as_uint(odd ? y1 : y0);
            pa[3] = __float_as_uint(odd ? y3 : y2);
#pragma unroll
            for (int nt = 0; nt < 8; nt++) {
                unsigned b0 = __float_as_uint(vs[(kk * 8 + tq) * VS_STR + nt * 8 + g]);
                unsigned b1 = __float_as_uint(vs[(kk * 8 + tq + 4) * VS_STR + nt * 8 + g]);
                mma_tf32(o[nt], pa, b0, b1);
            }
        }
    }

    float inv0 = 1.f / l0, inv1 = 1.f / l1;
#pragma unroll
    for (int nt = 0; nt < 8; nt++) {
        float2 w0 = make_float2(o[nt][0] * inv0, o[nt][1] * inv0);
        float2 w1 = make_float2(o[nt][2] * inv1, o[nt][3] * inv1);
        *(float2*)(O + (size_t)(tokBase + qrow0) * D_MODEL + h * 64 + nt * 8 + 2 * tq) = w0;
        *(float2*)(O + (size_t)(tokBase + qrow1) * D_MODEL + h * 64 + nt * 8 + 2 * tq) = w1;
    }
}

// ----------------------------------------------------------------------------
extern "C" void kernel_launch(void* const* d_in, const int* in_sizes, int n_in,
                              void* d_out, int out_size) {
    const float* x     = (const float*)d_in[0];
    const int*   rules = (const int*)  d_in[1];
    const float* q_si = (const float*)d_in[2],  *q_so = (const float*)d_in[3];
    const float* q_ri = (const float*)d_in[4],  *q_ro = (const float*)d_in[5];
    const float* q_lg = (const float*)d_in[6];
    const float* k_si = (const float*)d_in[7],  *k_so = (const float*)d_in[8];
    const float* k_ri = (const float*)d_in[9],  *k_ro = (const float*)d_in[10];
    const float* k_lg = (const float*)d_in[11];
    const float* v_si = (const float*)d_in[12], *v_so = (const float*)d_in[13];
    const float* v_ri = (const float*)d_in[14], *v_ro = (const float*)d_in[15];
    const float* v_lg = (const float*)d_in[16];
    const float* o_si = (const float*)d_in[17], *o_so = (const float*)d_in[18];
    const float* o_ri = (const float*)d_in[19], *o_ro = (const float*)d_in[20];
    const float* o_lg = (const float*)d_in[21];
    const float* router_q = (const float*)d_in[22];
    const float* router_k = (const float*)d_in[23];
    float* out = (float*)d_out;

    float *T1, *Qb, *Kb, *Vb, *AO, *Atab;
    float2* Rope;
    unsigned long long* Allow;
    cudaGetSymbolAddress((void**)&T1,    g_T1);
    cudaGetSymbolAddress((void**)&Qb,    g_Q);
    cudaGetSymbolAddress((void**)&Kb,    g_K);
    cudaGetSymbolAddress((void**)&Vb,    g_V);
    cudaGetSymbolAddress((void**)&AO,    g_AO);
    cudaGetSymbolAddress((void**)&Atab,  g_A);
    cudaGetSymbolAddress((void**)&Allow, g_allow);
    cudaGetSymbolAddress((void**)&Rope,  g_rope);

    aff_kernel<<<16, 256>>>(router_q, router_k, Atab);
    rope_kernel<<<64, 512>>>(Rope);
    thr_allow_kernel<<<NTOK, 64>>>(rules, Atab, Allow);

    // QKV base projections (batched z=3)
    gemm1_kernel<<<dim3(128, 1, 3), 128>>>(x, q_si, k_si, v_si, T1);
    gemm2_kernel<<<dim3(64, 16, 3), 256>>>(T1, q_so, k_so, v_so, Qb, Kb, Vb);

    AdpArgs aq;
    aq.ri[0] = q_ri; aq.ri[1] = k_ri; aq.ri[2] = v_ri;
    aq.ro[0] = q_ro; aq.ro[1] = k_ro; aq.ro[2] = v_ro;
    aq.lg[0] = q_lg; aq.lg[1] = k_lg; aq.lg[2] = v_lg;
    aq.base[0] = Qb; aq.base[1] = Kb; aq.base[2] = Vb;
    aq.nproj = 3; aq.ropemask = 0x3; aq.tfmask = 0x7;   // rope q,k; tf32-round q,k,v
    adapter_kernel<<<NTOK, 128>>>(x, rules, Rope, aq);

    // flash attention (tf32 tensor cores, cp.async double-buffered)
    cudaFuncSetAttribute(flash_tc, cudaFuncAttributeMaxDynamicSharedMemorySize, FLASH_SMEM);
    flash_tc<<<dim3(16, 64), 128, FLASH_SMEM>>>(Qb, Kb, Vb, rules, Allow, AO);

    // O projection
    gemm1_kernel<<<dim3(128, 1, 1), 128>>>(AO, o_si, o_si, o_si, T1);
    gemm2_kernel<<<dim3(64, 16, 1), 256>>>(T1, o_so, o_so, o_so, out, out, out);

    AdpArgs ao;
    ao.ri[0] = o_ri; ao.ri[1] = o_ri; ao.ri[2] = o_ri;
    ao.ro[0] = o_ro; ao.ro[1] = o_ro; ao.ro[2] = o_ro;
    ao.lg[0] = o_lg; ao.lg[1] = o_lg; ao.lg[2] = o_lg;
    ao.base[0] = out; ao.base[1] = out; ao.base[2] = out;
    ao.nproj = 1; ao.ropemask = 0; ao.tfmask = 0;
    adapter_kernel<<<NTOK, 128>>>(AO, rules, Rope, ao);
}

// round 4
// speedup vs baseline: 2.0504x; 1.1361x over previous
#include <cuda_runtime.h>
#include <math.h>

#define D_MODEL 1024
#define S_LEN   1024
#define BATCH   4
#define NTOK    4096
#define NHEADS  16
#define HD      64
#define NRULES  64
#define RANK    8
#define SRANK   32
#define NBLK    16
#define TOPK    32
#define KSPLIT  8

#define NEGINF (__int_as_float(0xff800000))

// ---------------- scratch (device globals; no allocation allowed) ------------
__device__ float g_T1[3 * NTOK * SRANK];
__device__ float g_P [KSPLIT * 3 * NTOK * SRANK];
__device__ float g_Q [NTOK * D_MODEL];
__device__ float g_K [NTOK * D_MODEL];
__device__ float g_V [NTOK * D_MODEL];
__device__ float g_AO[NTOK * D_MODEL];
__device__ float g_A [NRULES * NRULES];
__device__ unsigned long long g_allow[NTOK];
__device__ float2 g_rope[S_LEN * 32];

__device__ __forceinline__ unsigned f2tf(float x) {
    unsigned u;
    asm("cvt.rna.tf32.f32 %0, %1;" : "=r"(u) : "f"(x));
    return u;
}

__device__ __forceinline__ void mma_tf32(float d[4], const unsigned a[4],
                                         unsigned b0, unsigned b1) {
    asm volatile(
        "mma.sync.aligned.m16n8k8.row.col.f32.tf32.tf32.f32 "
        "{%0,%1,%2,%3}, {%4,%5,%6,%7}, {%8,%9}, {%0,%1,%2,%3};\n"
        : "+f"(d[0]), "+f"(d[1]), "+f"(d[2]), "+f"(d[3])
        : "r"(a[0]), "r"(a[1]), "r"(a[2]), "r"(a[3]), "r"(b0), "r"(b1));
}

__device__ __forceinline__ void cp16(float* smem_dst, const float* gsrc) {
    unsigned s = (unsigned)__cvta_generic_to_shared(smem_dst);
    asm volatile("cp.async.cg.shared.global [%0], [%1], 16;" :: "r"(s), "l"(gsrc));
}
__device__ __forceinline__ void cp_commit() {
    asm volatile("cp.async.commit_group;");
}
template <int N>
__device__ __forceinline__ void cp_wait() {
    asm volatile("cp.async.wait_group %0;" :: "n"(N));
}

// ---------------- affinity table ---------------------------------------------
__global__ void aff_kernel(const float* __restrict__ rq, const float* __restrict__ rk,
                           float* __restrict__ A) {
    int idx = blockIdx.x * blockDim.x + threadIdx.x;
    if (idx >= NRULES * NRULES) return;
    int i = idx >> 6, j = idx & 63;
    float qv[RANK], kv[RANK];
    float nq = 0.f, nk = 0.f;
#pragma unroll
    for (int r = 0; r < RANK; r++) {
        qv[r] = rq[i * RANK + r]; kv[r] = rk[j * RANK + r];
        nq += qv[r] * qv[r];      nk += kv[r] * kv[r];
    }
    float iq = 1.f / fmaxf(sqrtf(nq), 1e-12f);
    float ik = 1.f / fmaxf(sqrtf(nk), 1e-12f);
    float dot = 0.f;
#pragma unroll
    for (int r = 0; r < RANK; r++) dot += (qv[r] * iq) * (kv[r] * ik);
    A[idx] = dot * 2.0794415416798357f;
}

// ---------------- rope table --------------------------------------------------
__global__ void rope_kernel(float2* __restrict__ tab) {
    int idx = blockIdx.x * blockDim.x + threadIdx.x;
    if (idx >= S_LEN * 32) return;
    int spos = idx >> 5, i = idx & 31;
    float div = expf((float)(2 * i) * (-0.14391156831212786f)); // -ln(1e4)/64
    float ang = (float)spos * div;
    float sn, cs;
    sincosf(ang, &sn, &cs);
    tab[idx] = make_float2(cs, sn);
}

// --------- per-(b,q): top-32 threshold + allowed-rule 64-bit mask ------------
__global__ void thr_allow_kernel(const int* __restrict__ rules, const float* __restrict__ A,
                                 unsigned long long* __restrict__ allow) {
    int bq = blockIdx.x;
    int b = bq >> 10, q = bq & 1023;
    __shared__ int   cnt[NRULES];
    __shared__ float row[NRULES];
    __shared__ float thr_s;
    __shared__ unsigned bits[2];
    int t = threadIdx.x;      // 64 threads
    cnt[t] = 0;
    if (t == 0) thr_s = NEGINF;
    __syncthreads();
    const int* rb = rules + b * S_LEN;
    for (int k = t; k <= q; k += 64) atomicAdd(&cnt[rb[k]], 1);
    row[t] = A[rb[q] * NRULES + t];
    __syncthreads();
    if (q >= TOPK - 1) {
        float v = row[t];
        int   c = cnt[t];
        int greater = 0;
#pragma unroll 8
        for (int r = 0; r < NRULES; r++) greater += (row[r] > v) ? cnt[r] : 0;
        if (c > 0 && greater < TOPK && greater + c >= TOPK)
            thr_s = v;
    }
    __syncthreads();
    unsigned bal = __ballot_sync(0xffffffffu, row[t] >= thr_s);
    if ((t & 31) == 0) bits[t >> 5] = bal;
    __syncthreads();
    if (t == 0)
        allow[bq] = (unsigned long long)bits[0] | ((unsigned long long)bits[1] << 32);
}

// -------- GEMM1 (split-K, merged z): P[ks][z][4096,32] partials --------------
template <int NZ>
__global__ void __launch_bounds__(256)
gemm1_kernel(const float* __restrict__ X, const float* __restrict__ W0,
             const float* __restrict__ W1, const float* __restrict__ W2,
             float* __restrict__ P) {
    __shared__ float As[64][36];
    __shared__ float Bt[NZ][32][36];
    const float* Ws[3] = {W0, W1, W2};
    int tid = threadIdx.x;
    int tx = tid & 7, ty = tid >> 3;           // tx: 8 col-quads, ty: 0..31
    int rowBase = blockIdx.x * 64;
    int kBase = blockIdx.y * (D_MODEL / KSPLIT);

    float acc[NZ][2][4];
#pragma unroll
    for (int z = 0; z < NZ; z++)
#pragma unroll
        for (int i = 0; i < 2; i++)
#pragma unroll
            for (int j = 0; j < 4; j++) acc[z][i][j] = 0.f;

    for (int k0 = kBase; k0 < kBase + D_MODEL / KSPLIT; k0 += 32) {
#pragma unroll
        for (int i = 0; i < 2; i++) {          // A: 64x32 = 512 float4
            int f = tid + i * 256;
            int r = f >> 3, kq = f & 7;
            float4 v = *(const float4*)(X + (size_t)(rowBase + r) * D_MODEL + k0 + kq * 4);
            *(float4*)&As[r][kq * 4] = v;
        }
#pragma unroll
        for (int z = 0; z < NZ; z++)
#pragma unroll
            for (int i = 0; i < 4; i++) {      // B transposed: 32x32 each
                int f = tid + i * 256;
                int k = f >> 5, c = f & 31;
                Bt[z][c][k] = Ws[z][(size_t)(k0 + k) * SRANK + c];
            }
        __syncthreads();
#pragma unroll
        for (int kq = 0; kq < 8; kq++) {
            float4 a0 = *(float4*)&As[ty][kq * 4];
            float4 a1 = *(float4*)&As[ty + 32][kq * 4];
#pragma unroll
            for (int z = 0; z < NZ; z++) {
#pragma unroll
                for (int j = 0; j < 4; j++) {
                    float4 b = *(float4*)&Bt[z][tx + 8 * j][kq * 4];
                    acc[z][0][j] += a0.x * b.x + a0.y * b.y + a0.z * b.z + a0.w * b.w;
                    acc[z][1][j] += a1.x * b.x + a1.y * b.y + a1.z * b.z + a1.w * b.w;
                }
            }
        }
        __syncthreads();
    }
#pragma unroll
    for (int z = 0; z < NZ; z++)
#pragma unroll
        for (int i = 0; i < 2; i++)
#pragma unroll
            for (int j = 0; j < 4; j++)
                P[((size_t)(blockIdx.y * 3 + z) * NTOK + rowBase + ty + 32 * i) * SRANK
                  + tx + 8 * j] = acc[z][i][j];
}

__global__ void reduce_kernel(const float* __restrict__ P, float* __restrict__ T, int nz) {
    int idx = blockIdx.x * blockDim.x + threadIdx.x;
    if (idx >= nz * NTOK * SRANK) return;
    int z = idx / (NTOK * SRANK);
    int off = idx - z * (NTOK * SRANK);
    float s = 0.f;
#pragma unroll
    for (int ks = 0; ks < KSPLIT; ks++)
        s += P[(size_t)(ks * 3 + z) * NTOK * SRANK + off];
    T[(size_t)z * NTOK * SRANK + off] = s;
}

// ---------------- GEMM2: C_z[4096,1024] = T[z][4096,32] * W_z[32,1024] -------
__global__ void __launch_bounds__(256)
gemm2_kernel(const float* __restrict__ T, const float* __restrict__ W0,
             const float* __restrict__ W1, const float* __restrict__ W2,
             float* __restrict__ C0, float* __restrict__ C1, float* __restrict__ C2) {
    __shared__ float As[64][36];
    __shared__ float Bt[64][36];
    int tid = threadIdx.x;
    int tx = tid & 15, ty = tid >> 4;
    int z = blockIdx.z;
    const float* W = (z == 0) ? W0 : (z == 1) ? W1 : W2;
    float* C = (z == 0) ? C0 : (z == 1) ? C1 : C2;
    const float* A = T + (size_t)z * NTOK * SRANK;
    int rowBase = blockIdx.x * 64, colBase = blockIdx.y * 64;

#pragma unroll
    for (int i = 0; i < 2; i++) {
        int f = tid + i * 256;
        int r = f >> 3, kq = f & 7;
        float4 v = *(const float4*)(A + (size_t)(rowBase + r) * SRANK + kq * 4);
        *(float4*)&As[r][kq * 4] = v;
    }
#pragma unroll
    for (int i = 0; i < 8; i++) {
        int f = tid + i * 256;
        int k = f >> 6, c = f & 63;
        Bt[c][k] = W[(size_t)k * D_MODEL + colBase + c];
    }
    __syncthreads();

    float acc[4][4];
#pragma unroll
    for (int i = 0; i < 4; i++)
#pragma unroll
        for (int j = 0; j < 4; j++) acc[i][j] = 0.f;
#pragma unroll
    for (int kq = 0; kq < 8; kq++) {
        float4 a[4], bb[4];
#pragma unroll
        for (int i = 0; i < 4; i++) a[i]  = *(float4*)&As[ty + 16 * i][kq * 4];
#pragma unroll
        for (int j = 0; j < 4; j++) bb[j] = *(float4*)&Bt[tx + 16 * j][kq * 4];
#pragma unroll
        for (int i = 0; i < 4; i++)
#pragma unroll
            for (int j = 0; j < 4; j++)
                acc[i][j] += a[i].x * bb[j].x + a[i].y * bb[j].y
                           + a[i].z * bb[j].z + a[i].w * bb[j].w;
    }
#pragma unroll
    for (int i = 0; i < 4; i++)
#pragma unroll
        for (int j = 0; j < 4; j++)
            C[(size_t)(rowBase + ty + 16 * i) * D_MODEL + colBase + tx + 16 * j] = acc[i][j];
}

// -------- adapters (up to 3 projections per block, sharing the x load) -------
struct AdpArgs {
    const float* ri[3];
    const float* ro[3];
    const float* lg[3];
    float*       base[3];
    int nproj;
    int ropemask;
    int tfmask;
};

__global__ void __launch_bounds__(128)
adapter_kernel(const float* __restrict__ X, const int* __restrict__ rules,
               const float2* __restrict__ rope, AdpArgs A) {
    __shared__ float xs[D_MODEL];
    __shared__ float ris[HD * RANK];
    __shared__ float ros[RANK * HD];
    __shared__ float hs[NBLK * RANK];
    __shared__ float sels[NBLK];
    int n = blockIdx.x;
    int t = threadIdx.x;
    int rule = rules[n];

    const float4* x4 = (const float4*)(X + (size_t)n * D_MODEL);
    float4* xs4 = (float4*)xs;
    xs4[t] = x4[t];
    xs4[t + 128] = x4[t + 128];

    int spos = n & (S_LEN - 1);
    int d0 = t * 8;
    int dh0 = d0 & 63;
    int blk = t >> 3;

    for (int p = 0; p < A.nproj; p++) {
#pragma unroll
        for (int i = 0; i < 4; i++) {
            ris[t + i * 128] = A.ri[p][rule * 512 + t + i * 128];
            ros[t + i * 128] = A.ro[p][rule * 512 + t + i * 128];
        }
        if (t < 32) {
            int j = t & 15;
            float v = A.lg[p][rule * NBLK + j] * 4.0f;
            float mx = v;
#pragma unroll
            for (int msk = 8; msk >= 1; msk >>= 1)
                mx = fmaxf(mx, __shfl_xor_sync(0xffffffffu, mx, msk));
            float e = expf(v - mx);
            float sm2 = e;
#pragma unroll
            for (int msk = 8; msk >= 1; msk >>= 1)
                sm2 += __shfl_xor_sync(0xffffffffu, sm2, msk);
            if (t < 16) sels[t] = e / sm2;
        }
        __syncthreads();
        {
            int bb = t >> 3, r = t & 7;
            float sum = 0.f;
#pragma unroll
            for (int sx = 0; sx < 64; sx++) sum += xs[bb * 64 + sx] * ris[sx * 8 + r];
            hs[t] = sum;
        }
        __syncthreads();
        float hl[8];
#pragma unroll
        for (int r = 0; r < 8; r++) hl[r] = hs[blk * 8 + r];
        float selv = sels[blk];
        float* Base = A.base[p];
        float4 b0 = *(float4*)(Base + (size_t)n * D_MODEL + d0);
        float4 b1 = *(float4*)(Base + (size_t)n * D_MODEL + d0 + 4);
        float outv[8] = {b0.x, b0.y, b0.z, b0.w, b1.x, b1.y, b1.z, b1.w};
        float av[8] = {0.f, 0.f, 0.f, 0.f, 0.f, 0.f, 0.f, 0.f};
#pragma unroll
        for (int r = 0; r < 8; r++) {
            float4 r0 = *(float4*)&ros[r * 64 + dh0];
            float4 r1 = *(float4*)&ros[r * 64 + dh0 + 4];
            av[0] += hl[r] * r0.x; av[1] += hl[r] * r0.y;
            av[2] += hl[r] * r0.z; av[3] += hl[r] * r0.w;
            av[4] += hl[r] * r1.x; av[5] += hl[r] * r1.y;
            av[6] += hl[r] * r1.z; av[7] += hl[r] * r1.w;
        }
#pragma unroll
        for (int c = 0; c < 8; c++) outv[c] += av[c] * selv;
        if ((A.ropemask >> p) & 1) {
#pragma unroll
            for (int pp = 0; pp < 4; pp++) {
                int i = (dh0 + 2 * pp) >> 1;
                float2 cs = __ldg(&rope[spos * 32 + i]);
                float t1 = outv[2 * pp], t2 = outv[2 * pp + 1];
                outv[2 * pp]     = t1 * cs.x - t2 * cs.y;
                outv[2 * pp + 1] = t2 * cs.x + t1 * cs.y;
            }
        }
        if ((A.tfmask >> p) & 1) {
#pragma unroll
            for (int c = 0; c < 8; c++) outv[c] = __uint_as_float(f2tf(outv[c]));
        }
        *(float4*)(Base + (size_t)n * D_MODEL + d0)     = make_float4(outv[0], outv[1], outv[2], outv[3]);
        *(float4*)(Base + (size_t)n * D_MODEL + d0 + 4) = make_float4(outv[4], outv[5], outv[6], outv[7]);
        __syncthreads();
    }
}

// ------------------------- flash attention (tf32 MMA) ------------------------
// Q fragments loaded once per CTA directly from gmem (Q already tf32).
// K/V double-buffered via cp.async. smem ~70.5KB -> 3 CTAs/SM.
#define QS_STR 68
#define VS_STR 72
#define FLASH_SMEM ((2 * 64 * QS_STR + 2 * 64 * VS_STR + 128) * 4)

__global__ void __launch_bounds__(128)
flash_tc(const float* __restrict__ Q, const float* __restrict__ K,
         const float* __restrict__ V, const int* __restrict__ rules,
         const unsigned long long* __restrict__ allow, float* __restrict__ O) {
    extern __shared__ float sm[];
    float* ksb[2]; float* vsb[2]; int* rkb[2];
    ksb[0] = sm;
    ksb[1] = ksb[0] + 64 * QS_STR;
    vsb[0] = ksb[1] + 64 * QS_STR;
    vsb[1] = vsb[0] + 64 * VS_STR;
    rkb[0] = (int*)(vsb[1] + 64 * VS_STR);
    rkb[1] = rkb[0] + 64;

    const int tid  = threadIdx.x;
    const int warp = tid >> 5, lane = tid & 31;
    const int g = lane >> 2, tq = lane & 3;
    const int qt = gridDim.x - 1 - blockIdx.x;     // heavy blocks first
    const int b = blockIdx.y >> 4, h = blockIdx.y & 15;
    const int tokBase = b * S_LEN;
    const int rbase = warp * 16;

    const int ldr = tid >> 4, ldc = (tid & 15) * 4;

    // ---- issue async copy of tile 0 ----
    {
        float* ks = ksb[0]; float* vs = vsb[0];
#pragma unroll
        for (int i = 0; i < 8; i++) {
            int r = ldr + i * 8;
            size_t go = (size_t)(tokBase + r) * D_MODEL + h * 64 + ldc;
            cp16(ks + r * QS_STR + ldc, K + go);
            cp16(vs + r * VS_STR + ldc, V + go);
        }
        cp_commit();
        if (tid < 64) rkb[0][tid] = rules[tokBase + tid];
    }

    const int qrow0 = qt * 64 + rbase + g;
    const int qrow1 = qrow0 + 8;

    // ---- Q fragments direct from gmem (already tf32) ----
    unsigned qa[8][4];
    {
        const float* Qr0 = Q + (size_t)(tokBase + qrow0) * D_MODEL + h * 64;
        const float* Qr1 = Q + (size_t)(tokBase + qrow1) * D_MODEL + h * 64;
#pragma unroll
        for (int kk = 0; kk < 8; kk++) {
            qa[kk][0] = __float_as_uint(Qr0[kk * 8 + tq]);
            qa[kk][1] = __float_as_uint(Qr1[kk * 8 + tq]);
            qa[kk][2] = __float_as_uint(Qr0[kk * 8 + tq + 4]);
            qa[kk][3] = __float_as_uint(Qr1[kk * 8 + tq + 4]);
        }
    }

    const unsigned long long al0 = allow[b * S_LEN + qrow0];
    const unsigned long long al1 = allow[b * S_LEN + qrow1];

    float o[8][4];
#pragma unroll
    for (int nt = 0; nt < 8; nt++)
#pragma unroll
        for (int j = 0; j < 4; j++) o[nt][j] = 0.f;
    float m0 = NEGINF, m1 = NEGINF, l0 = 0.f, l1 = 0.f;

    for (int kt = 0; kt <= qt; kt++) {
        const int buf = kt & 1;
        __syncthreads();                 // prior compute done before refilling buf^1
        if (kt < qt) {
            float* ks = ksb[buf ^ 1]; float* vs = vsb[buf ^ 1];
#pragma unroll
            for (int i = 0; i < 8; i++) {
                int r = ldr + i * 8;
                size_t go = (size_t)(tokBase + (kt + 1) * 64 + r) * D_MODEL + h * 64 + ldc;
                cp16(ks + r * QS_STR + ldc, K + go);
                cp16(vs + r * VS_STR + ldc, V + go);
            }
            cp_commit();
            if (tid < 64) rkb[buf ^ 1][tid] = rules[tokBase + (kt + 1) * 64 + tid];
            cp_wait<1>();
        } else {
            cp_wait<0>();
        }
        __syncthreads();

        const float* ks = ksb[buf];
        const float* vs = vsb[buf];
        const int*   rk_s = rkb[buf];

        // ---- S = Q K^T ----
        float s[8][4];
#pragma unroll
        for (int nt = 0; nt < 8; nt++)
#pragma unroll
            for (int j = 0; j < 4; j++) s[nt][j] = 0.f;
#pragma unroll
        for (int kk = 0; kk < 8; kk++) {
#pragma unroll
            for (int nt = 0; nt < 8; nt++) {
                unsigned b0 = __float_as_uint(ks[(nt * 8 + g) * QS_STR + kk * 8 + tq]);
                unsigned b1 = __float_as_uint(ks[(nt * 8 + g) * QS_STR + kk * 8 + tq + 4]);
                mma_tf32(s[nt], qa[kk], b0, b1);
            }
        }

        // ---- mask + scale ----
        const bool diag = (kt == qt);
#pragma unroll
        for (int nt = 0; nt < 8; nt++) {
            int c0 = nt * 8 + 2 * tq;
            int rk0 = rk_s[c0], rk1 = rk_s[c0 + 1];
            int col0 = kt * 64 + c0;
            bool ok00 = ((al0 >> rk0) & 1ULL) && (!diag || col0 <= qrow0);
            bool ok01 = ((al0 >> rk1) & 1ULL) && (!diag || col0 + 1 <= qrow0);
            bool ok10 = ((al1 >> rk0) & 1ULL) && (!diag || col0 <= qrow1);
            bool ok11 = ((al1 >> rk1) & 1ULL) && (!diag || col0 + 1 <= qrow1);
            s[nt][0] = ok00 ? s[nt][0] * 0.125f : NEGINF;
            s[nt][1] = ok01 ? s[nt][1] * 0.125f : NEGINF;
            s[nt][2] = ok10 ? s[nt][2] * 0.125f : NEGINF;
            s[nt][3] = ok11 ? s[nt][3] * 0.125f : NEGINF;
        }

        // ---- online softmax ----
        float mx0 = NEGINF, mx1 = NEGINF;
#pragma unroll
        for (int nt = 0; nt < 8; nt++) {
            mx0 = fmaxf(mx0, fmaxf(s[nt][0], s[nt][1]));
            mx1 = fmaxf(mx1, fmaxf(s[nt][2], s[nt][3]));
        }
        mx0 = fmaxf(mx0, __shfl_xor_sync(0xffffffffu, mx0, 1));
        mx0 = fmaxf(mx0, __shfl_xor_sync(0xffffffffu, mx0, 2));
        mx1 = fmaxf(mx1, __shfl_xor_sync(0xffffffffu, mx1, 1));
        mx1 = fmaxf(mx1, __shfl_xor_sync(0xffffffffu, mx1, 2));
        float mn0 = fmaxf(m0, mx0), mn1 = fmaxf(m1, mx1);
        float cr0 = (m0 == mn0) ? 1.f : __expf(m0 - mn0);
        float cr1 = (m1 == mn1) ? 1.f : __expf(m1 - mn1);
        float rs0 = 0.f, rs1 = 0.f;
        if (mn0 != NEGINF) {
#pragma unroll
            for (int nt = 0; nt < 8; nt++) {
                s[nt][0] = __expf(s[nt][0] - mn0);
                s[nt][1] = __expf(s[nt][1] - mn0);
                rs0 += s[nt][0] + s[nt][1];
            }
        } else {
#pragma unroll
            for (int nt = 0; nt < 8; nt++) { s[nt][0] = 0.f; s[nt][1] = 0.f; }
        }
        if (mn1 != NEGINF) {
#pragma unroll
            for (int nt = 0; nt < 8; nt++) {
                s[nt][2] = __expf(s[nt][2] - mn1);
                s[nt][3] = __expf(s[nt][3] - mn1);
                rs1 += s[nt][2] + s[nt][3];
            }
        } else {
#pragma unroll
            for (int nt = 0; nt < 8; nt++) { s[nt][2] = 0.f; s[nt][3] = 0.f; }
        }
        rs0 += __shfl_xor_sync(0xffffffffu, rs0, 1);
        rs0 += __shfl_xor_sync(0xffffffffu, rs0, 2);
        rs1 += __shfl_xor_sync(0xffffffffu, rs1, 1);
        rs1 += __shfl_xor_sync(0xffffffffu, rs1, 2);
        l0 = l0 * cr0 + rs0;
        l1 = l1 * cr1 + rs1;
        m0 = mn0; m1 = mn1;
#pragma unroll
        for (int nt = 0; nt < 8; nt++) {
            o[nt][0] *= cr0; o[nt][1] *= cr0;
            o[nt][2] *= cr1; o[nt][3] *= cr1;
        }

        // ---- round P to tf32 ----
#pragma unroll
        for (int nt = 0; nt < 8; nt++)
#pragma unroll
            for (int j = 0; j < 4; j++)
                s[nt][j] = __uint_as_float(f2tf(s[nt][j]));

        // ---- O += P V  (P fragments gathered via quad shuffles) ----
        const unsigned srcA = (lane & 28) | (tq >> 1);
        const unsigned srcB = srcA + 2;
        const bool odd = (tq & 1);
#pragma unroll
        for (int kk = 0; kk < 8; kk++) {
            float x0 = __shfl_sync(0xffffffffu, s[kk][0], srcA);
            float x1 = __shfl_sync(0xffffffffu, s[kk][1], srcA);
            float x2 = __shfl_sync(0xffffffffu, s[kk][2], srcA);
            float x3 = __shfl_sync(0xffffffffu, s[kk][3], srcA);
            float y0 = __shfl_sync(0xffffffffu, s[kk][0], srcB);
            float y1 = __shfl_sync(0xffffffffu, s[kk][1], srcB);
            float y2 = __shfl_sync(0xffffffffu, s[kk][2], srcB);
            float y3 = __shfl_sync(0xffffffffu, s[kk][3], srcB);
            unsigned pa[4];
            pa[0] = __float_as_uint(odd ? x1 : x0);
            pa[1] = __float_as_uint(odd ? x3 : x2);
            pa[2] = __float_as_uint(odd ? y1 : y0);
            pa[3] = __float_as_uint(odd ? y3 : y2);
#pragma unroll
            for (int nt = 0; nt < 8; nt++) {
                unsigned b0 = __float_as_uint(vs[(kk * 8 + tq) * VS_STR + nt * 8 + g]);
                unsigned b1 = __float_as_uint(vs[(kk * 8 + tq + 4) * VS_STR + nt * 8 + g]);
                mma_tf32(o[nt], pa, b0, b1);
            }
        }
    }

    float inv0 = 1.f / l0, inv1 = 1.f / l1;
#pragma unroll
    for (int nt = 0; nt < 8; nt++) {
        float2 w0 = make_float2(o[nt][0] * inv0, o[nt][1] * inv0);
        float2 w1 = make_float2(o[nt][2] * inv1, o[nt][3] * inv1);
        *(float2*)(O + (size_t)(tokBase + qrow0) * D_MODEL + h * 64 + nt * 8 + 2 * tq) = w0;
        *(float2*)(O + (size_t)(tokBase + qrow1) * D_MODEL + h * 64 + nt * 8 + 2 * tq) = w1;
    }
}

// ----------------------------------------------------------------------------
extern "C" void kernel_launch(void* const* d_in, const int* in_sizes, int n_in,
                              void* d_out, int out_size) {
    const float* x     = (const float*)d_in[0];
    const int*   rules = (const int*)  d_in[1];
    const float* q_si = (const float*)d_in[2],  *q_so = (const float*)d_in[3];
    const float* q_ri = (const float*)d_in[4],  *q_ro = (const float*)d_in[5];
    const float* q_lg = (const float*)d_in[6];
    const float* k_si = (const float*)d_in[7],  *k_so = (const float*)d_in[8];
    const float* k_ri = (const float*)d_in[9],  *k_ro = (const float*)d_in[10];
    const float* k_lg = (const float*)d_in[11];
    const float* v_si = (const float*)d_in[12], *v_so = (const float*)d_in[13];
    const float* v_ri = (const float*)d_in[14], *v_ro = (const float*)d_in[15];
    const float* v_lg = (const float*)d_in[16];
    const float* o_si = (const float*)d_in[17], *o_so = (const float*)d_in[18];
    const float* o_ri = (const float*)d_in[19], *o_ro = (const float*)d_in[20];
    const float* o_lg = (const float*)d_in[21];
    const float* router_q = (const float*)d_in[22];
    const float* router_k = (const float*)d_in[23];
    float* out = (float*)d_out;

    float *T1, *Pp, *Qb, *Kb, *Vb, *AO, *Atab;
    float2* Rope;
    unsigned long long* Allow;
    cudaGetSymbolAddress((void**)&T1,    g_T1);
    cudaGetSymbolAddress((void**)&Pp,    g_P);
    cudaGetSymbolAddress((void**)&Qb,    g_Q);
    cudaGetSymbolAddress((void**)&Kb,    g_K);
    cudaGetSymbolAddress((void**)&Vb,    g_V);
    cudaGetSymbolAddress((void**)&AO,    g_AO);
    cudaGetSymbolAddress((void**)&Atab,  g_A);
    cudaGetSymbolAddress((void**)&Allow, g_allow);
    cudaGetSymbolAddress((void**)&Rope,  g_rope);

    aff_kernel<<<16, 256>>>(router_q, router_k, Atab);
    rope_kernel<<<64, 512>>>(Rope);
    thr_allow_kernel<<<NTOK, 64>>>(rules, Atab, Allow);

    // QKV base projections (merged z, split-K)
    gemm1_kernel<3><<<dim3(64, KSPLIT), 256>>>(x, q_si, k_si, v_si, Pp);
    reduce_kernel<<<(3 * NTOK * SRANK + 255) / 256, 256>>>(Pp, T1, 3);
    gemm2_kernel<<<dim3(64, 16, 3), 256>>>(T1, q_so, k_so, v_so, Qb, Kb, Vb);

    AdpArgs aq;
    aq.ri[0] = q_ri; aq.ri[1] = k_ri; aq.ri[2] = v_ri;
    aq.ro[0] = q_ro; aq.ro[1] = k_ro; aq.ro[2] = v_ro;
    aq.lg[0] = q_lg; aq.lg[1] = k_lg; aq.lg[2] = v_lg;
    aq.base[0] = Qb; aq.base[1] = Kb; aq.base[2] = Vb;
    aq.nproj = 3; aq.ropemask = 0x3; aq.tfmask = 0x7;
    adapter_kernel<<<NTOK, 128>>>(x, rules, Rope, aq);

    // flash attention (tf32 tensor cores, cp.async double-buffered)
    cudaFuncSetAttribute(flash_tc, cudaFuncAttributeMaxDynamicSharedMemorySize, FLASH_SMEM);
    flash_tc<<<dim3(16, 64), 128, FLASH_SMEM>>>(Qb, Kb, Vb, rules, Allow, AO);

    // O projection
    gemm1_kernel<1><<<dim3(64, KSPLIT), 256>>>(AO, o_si, o_si, o_si, Pp);
    reduce_kernel<<<(NTOK * SRANK + 255) / 256, 256>>>(Pp, T1, 1);
    gemm2_kernel<<<dim3(64, 16, 1), 256>>>(T1, o_so, o_so, o_so, out, out, out);

    AdpArgs ao;
    ao.ri[0] = o_ri; ao.ri[1] = o_ri; ao.ri[2] = o_ri;
    ao.ro[0] = o_ro; ao.ro[1] = o_ro; ao.ro[2] = o_ro;
    ao.lg[0] = o_lg; ao.lg[1] = o_lg; ao.lg[2] = o_lg;
    ao.base[0] = out; ao.base[1] = out; ao.base[2] = out;
    ao.nproj = 1; ao.ropemask = 0; ao.tfmask = 0;
    adapter_kernel<<<NTOK, 128>>>(AO, rules, Rope, ao);
}